// round 7
// baseline (speedup 1.0000x reference)
#include <cuda_runtime.h>
#include <cuda_bf16.h>
#include <cstdint>

#define NN 100000
#define NE 1600000
#define NBLK_SCAN 98   // ceil(100000/1024)

// ---------------------------------------------------------------------------
// Scratch (static device arrays; allocation-free per harness rules).
// ---------------------------------------------------------------------------
__device__ float         g_S[(size_t)NN * 128];   // support (layer outputs), fp32
__device__ float         g_S2[(size_t)NN * 64];   // layer-2 support
__device__ float         g_S3[(size_t)NN * 64];   // layer-3 support
__device__ __nv_bfloat16 g_WH[45056];             // weight hi planes (W1T|W2T|W3T)
__device__ __nv_bfloat16 g_WL[45056];             // weight lo planes
__device__ int   g_cnt[NN];
__device__ int   g_pre[NN];
__device__ int   g_bsum[1024];
__device__ int   g_btop[1024];
__device__ int   g_rowptr[NN + 1];
__device__ int   g_cursor[NN];
__device__ int2  g_csr[NE];

// ---------------------------------------------------------------------------
// Helpers
// ---------------------------------------------------------------------------
__device__ __forceinline__ uint32_t smem_u32(const void* p) {
    uint32_t a;
    asm("{ .reg .u64 t; cvta.to.shared.u64 t, %1; cvt.u32.u64 %0, t; }" : "=r"(a) : "l"(p));
    return a;
}
__device__ __forceinline__ void cp16(uint32_t s, const void* g, bool pred) {
    asm volatile("cp.async.cg.shared.global [%0], [%1], 16, %2;"
                 :: "r"(s), "l"(g), "r"(pred ? 16 : 0));
}
#define CP_COMMIT() asm volatile("cp.async.commit_group;" ::: "memory")
#define CP_WAIT0()  asm volatile("cp.async.wait_group 0;" ::: "memory")
#define CP_WAIT1()  asm volatile("cp.async.wait_group 1;" ::: "memory")

__device__ __forceinline__ void ldsm4(uint32_t& r0, uint32_t& r1, uint32_t& r2, uint32_t& r3,
                                      uint32_t addr) {
    asm volatile("ldmatrix.sync.aligned.m8n8.x4.shared.b16 {%0,%1,%2,%3}, [%4];"
                 : "=r"(r0), "=r"(r1), "=r"(r2), "=r"(r3) : "r"(addr));
}
__device__ __forceinline__ void ldsm2(uint32_t& r0, uint32_t& r1, uint32_t addr) {
    asm volatile("ldmatrix.sync.aligned.m8n8.x2.shared.b16 {%0,%1}, [%2];"
                 : "=r"(r0), "=r"(r1) : "r"(addr));
}
__device__ __forceinline__ void mma_bf16(float* d, const uint32_t* a, const uint32_t* b) {
    asm volatile(
        "mma.sync.aligned.m16n8k16.row.col.f32.bf16.bf16.f32 "
        "{%0,%1,%2,%3}, {%4,%5,%6,%7}, {%8,%9}, {%0,%1,%2,%3};"
        : "+f"(d[0]), "+f"(d[1]), "+f"(d[2]), "+f"(d[3])
        : "r"(a[0]), "r"(a[1]), "r"(a[2]), "r"(a[3]), "r"(b[0]), "r"(b[1]));
}
__device__ __forceinline__ unsigned pack2bf(float a, float b) {
    __nv_bfloat162 t = make_bfloat162(__float2bfloat16_rn(a), __float2bfloat16_rn(b));
    return *reinterpret_cast<unsigned*>(&t);
}
__device__ __forceinline__ float bfres(float v) {
    return v - __bfloat162float(__float2bfloat16_rn(v));
}

// ---------------------------------------------------------------------------
// CSR build kernels (known good)
// ---------------------------------------------------------------------------
__global__ void zero_kernel(int* __restrict__ p, int n) {
    int i = blockIdx.x * blockDim.x + threadIdx.x;
    if (i < n) p[i] = 0;
}
__global__ void count_kernel(const int* __restrict__ dst, int* __restrict__ cnt, int E) {
    int e = blockIdx.x * blockDim.x + threadIdx.x;
    if (e < E) atomicAdd(&cnt[__ldg(&dst[e])], 1);
}
__global__ void scan_block_kernel(const int* __restrict__ in, int* __restrict__ outx,
                                  int* __restrict__ sums, int n) {
    __shared__ int s[2][1024];
    int tid = threadIdx.x;
    int i = blockIdx.x * 1024 + tid;
    int v = (i < n) ? in[i] : 0;
    int pin = 0;
    s[0][tid] = v;
    __syncthreads();
#pragma unroll
    for (int off = 1; off < 1024; off <<= 1) {
        int t = s[pin][tid] + ((tid >= off) ? s[pin][tid - off] : 0);
        s[pin ^ 1][tid] = t;
        pin ^= 1;
        __syncthreads();
    }
    if (i < n) outx[i] = s[pin][tid] - v;
    if (sums != nullptr && tid == 1023) sums[blockIdx.x] = s[pin][1023];
}
__global__ void add_offsets_kernel(const int* __restrict__ pre, const int* __restrict__ top,
                                   int* __restrict__ rowptr, int* __restrict__ cursor, int n) {
    int i = blockIdx.x * blockDim.x + threadIdx.x;
    if (i < n) {
        int v = pre[i] + __ldg(&top[i >> 10]);
        rowptr[i] = v;
        cursor[i] = v;
    }
    if (i == 0) rowptr[n] = NE;
}
__global__ void scatter_kernel(const int* __restrict__ src, const int* __restrict__ dst,
                               const float* __restrict__ w, int* __restrict__ cursor,
                               int2* __restrict__ csr, int E) {
    int e = blockIdx.x * blockDim.x + threadIdx.x;
    if (e >= E) return;
    int d = __ldg(&dst[e]);
    int pos = atomicAdd(&cursor[d], 1);
    csr[pos] = make_int2(__ldg(&src[e]), __float_as_int(__ldg(&w[e])));
}

// W[K,N] row-major -> planes [N,K] k-major
__global__ void wsplit_kernel(const float* __restrict__ W, __nv_bfloat16* __restrict__ hi,
                              __nv_bfloat16* __restrict__ lo, int K, int N) {
    int i = blockIdx.x * blockDim.x + threadIdx.x;
    if (i >= K * N) return;
    int n = i / K, k = i % K;
    float v = __ldg(&W[(size_t)k * N + n]);
    hi[(size_t)n * K + k] = __float2bfloat16_rn(v);
    lo[(size_t)n * K + k] = __float2bfloat16_rn(bfres(v));
}

// ---------------------------------------------------------------------------
// HMMA bf16-split GEMM (standalone, CONV path): C = fp32A @ (Bhi+Blo)^T
// BM=128, BK=32, double-buffered; 8 warps (2m x 4n). (Layer-1 only.)
// ---------------------------------------------------------------------------
template <int N_OUT, int K_TOTAL>
__global__ __launch_bounds__(256, 2)
void gemm_mma_kernel(const float* __restrict__ Af,
                     const __nv_bfloat16* __restrict__ Bhi, const __nv_bfloat16* __restrict__ Blo,
                     float* __restrict__ C, int M) {
    constexpr int NCH = K_TOTAL / 32;
    constexpr int ROWB = 80;
    constexpr int AT = 128 * ROWB;
    constexpr int BT = N_OUT * ROWB;
    constexpr int STAGE = 2 * AT + 2 * BT;
    constexpr int WN = N_OUT / 4;
    constexpr int NF = WN / 8;

    extern __shared__ char smem[];
    const uint32_t sb = smem_u32(smem);
    const int tid = threadIdx.x;
    const int wid = tid >> 5, lane = tid & 31;
    const int wm = wid & 1, wn = wid >> 1;
    const int bm = blockIdx.x * 128;
    const int lrow = lane & 7;
    const int lmat = lane >> 3;

    float acc[4][NF][4];
#pragma unroll
    for (int mf = 0; mf < 4; mf++)
#pragma unroll
        for (int nf = 0; nf < NF; nf++)
#pragma unroll
            for (int j = 0; j < 4; j++) acc[mf][nf][j] = 0.f;

    auto loadA = [&](int ch, int st) {
#pragma unroll
        for (int i = 0; i < 4; i++) {
            int idx = tid + i * 256;
            int row = idx >> 3, seg = idx & 7;
            float4 v = make_float4(0.f, 0.f, 0.f, 0.f);
            if (bm + row < M)
                v = __ldg((const float4*)&Af[(size_t)(bm + row) * K_TOTAL + ch * 32 + seg * 4]);
            uint2 h, l;
            h.x = pack2bf(v.x, v.y);  h.y = pack2bf(v.z, v.w);
            l.x = pack2bf(bfres(v.x), bfres(v.y));
            l.y = pack2bf(bfres(v.z), bfres(v.w));
            uint32_t off = row * ROWB + seg * 8;
            *(uint2*)(smem + st * STAGE + off) = h;
            *(uint2*)(smem + st * STAGE + AT + off) = l;
        }
    };
    auto loadB = [&](int ch, int st) {
        const uint32_t base = sb + st * STAGE;
#pragma unroll
        for (int i = 0; i < (N_OUT * 4) / 256; i++) {
            int idx = tid + i * 256;
            int row = idx >> 2, seg = idx & 3;
            size_t g = (size_t)row * K_TOTAL + ch * 32 + seg * 8;
            cp16(base + 2 * AT + row * ROWB + seg * 16, Bhi + g, true);
            cp16(base + 2 * AT + BT + row * ROWB + seg * 16, Blo + g, true);
        }
        CP_COMMIT();
    };
    auto compute = [&](int st) {
        const uint32_t base = sb + st * STAGE;
        const uint32_t aHi = base, aLo = base + AT;
        const uint32_t bHi = base + 2 * AT, bLo = base + 2 * AT + BT;
#pragma unroll
        for (int ks = 0; ks < 2; ks++) {
            const int seg = 2 * ks + (lmat >> 1);
            uint32_t bh[NF][2], bl[NF][2];
#pragma unroll
            for (int p = 0; p < NF / 2; p++) {
                int nrow = wn * WN + p * 16 + lrow + (lmat & 1) * 8;
                uint32_t off = nrow * ROWB + seg * 16;
                uint32_t r0, r1, r2, r3;
                ldsm4(r0, r1, r2, r3, bHi + off);
                bh[2 * p][0] = r0; bh[2 * p + 1][0] = r1;
                bh[2 * p][1] = r2; bh[2 * p + 1][1] = r3;
                ldsm4(r0, r1, r2, r3, bLo + off);
                bl[2 * p][0] = r0; bl[2 * p + 1][0] = r1;
                bl[2 * p][1] = r2; bl[2 * p + 1][1] = r3;
            }
#pragma unroll
            for (int mf = 0; mf < 4; mf++) {
                int arow = wm * 64 + mf * 16 + lrow + (lmat & 1) * 8;
                uint32_t off = arow * ROWB + seg * 16;
                uint32_t ah[4], al[4];
                ldsm4(ah[0], ah[1], ah[2], ah[3], aHi + off);
                ldsm4(al[0], al[1], al[2], al[3], aLo + off);
#pragma unroll
                for (int nf = 0; nf < NF; nf++) {
                    mma_bf16(acc[mf][nf], ah, bh[nf]);
                    mma_bf16(acc[mf][nf], ah, bl[nf]);
                    mma_bf16(acc[mf][nf], al, bh[nf]);
                }
            }
        }
    };

    loadA(0, 0);
    loadB(0, 0);
    for (int c = 0; c < NCH; c++) {
        if (c + 1 < NCH) {
            loadA(c + 1, (c + 1) & 1);
            loadB(c + 1, (c + 1) & 1);
            CP_WAIT1();
        } else {
            CP_WAIT0();
        }
        __syncthreads();
        compute(c & 1);
        __syncthreads();
    }

    const int r0 = lane >> 2;
    const int c0 = (lane & 3) * 2;
#pragma unroll
    for (int mf = 0; mf < 4; mf++) {
        int row = bm + wm * 64 + mf * 16 + r0;
#pragma unroll
        for (int half = 0; half < 2; half++) {
            int rr = row + half * 8;
            if (rr < M) {
#pragma unroll
                for (int nf = 0; nf < NF; nf++) {
                    float2 v = make_float2(acc[mf][nf][half * 2], acc[mf][nf][half * 2 + 1]);
                    *(float2*)&C[(size_t)rr * N_OUT + wn * WN + nf * 8 + c0] = v;
                }
            }
        }
    }
}

// ---------------------------------------------------------------------------
// Fused SpMM + GEMM: per block (1024 thr), 128 dst nodes.
// Phase 1: warp = 4 nodes, pull-mode aggregate (bias+relu), pack hi/lo bf16
//          directly into smem ldmatrix layout. B planes prefetched via cp.async.
// Phase 2: HMMA split-GEMM from smem, write next support (fp32).
// N_OUT must be 64. K_IN in {64, 128}.
// ---------------------------------------------------------------------------
template <int K_IN, int N_OUT>
__global__ __launch_bounds__(1024, 1)
void fused_spmm_gemm_kernel(const float* __restrict__ S, const int2* __restrict__ csr,
                            const int* __restrict__ rowptr, const float* __restrict__ bias,
                            const __nv_bfloat16* __restrict__ Bhi,
                            const __nv_bfloat16* __restrict__ Blo,
                            float* __restrict__ Sout, int M) {
    constexpr int NCH = K_IN / 32;
    constexpr int ROWB = 80;
    constexpr int ACH = 128 * ROWB;          // 10240 per chunk-plane
    constexpr int BCH = N_OUT * ROWB;        // 5120 per chunk-plane
    constexpr int A_LO = NCH * ACH;
    constexpr int B_HI = 2 * NCH * ACH;
    constexpr int B_LO = B_HI + NCH * BCH;

    extern __shared__ char smem[];
    const uint32_t sb = smem_u32(smem);
    const int tid = threadIdx.x;
    const int wid = tid >> 5, lane = tid & 31;
    const int bm = blockIdx.x * 128;

    // Prefetch B planes (overlaps with phase 1)
    for (int idx = tid; idx < NCH * N_OUT * 4; idx += 1024) {
        int ch = idx / (N_OUT * 4);
        int rem = idx % (N_OUT * 4);
        int row = rem >> 2, seg = rem & 3;
        size_t g = (size_t)row * K_IN + ch * 32 + seg * 8;
        cp16(sb + B_HI + ch * BCH + row * ROWB + seg * 16, Bhi + g, true);
        cp16(sb + B_LO + ch * BCH + row * ROWB + seg * 16, Blo + g, true);
    }
    CP_COMMIT();

    // ---- Phase 1: SpMM (bias + relu), pack to smem ----
#pragma unroll
    for (int i = 0; i < 4; i++) {
        int lnode = wid * 4 + i;             // 0..127
        int node = bm + lnode;
        int start = 0, end = 0;
        if (node < M) { start = __ldg(&rowptr[node]); end = __ldg(&rowptr[node + 1]); }
        if (K_IN == 128) {
            float4 acc = __ldg((const float4*)bias + lane);
            int e = start;
            for (; e + 1 < end; e += 2) {
                int2 r0 = __ldg(&csr[e]);
                int2 r1 = __ldg(&csr[e + 1]);
                float4 v0 = __ldg((const float4*)(S + (size_t)r0.x * 128) + lane);
                float4 v1 = __ldg((const float4*)(S + (size_t)r1.x * 128) + lane);
                float w0 = __int_as_float(r0.y), w1 = __int_as_float(r1.y);
                acc.x = fmaf(w0, v0.x, acc.x); acc.y = fmaf(w0, v0.y, acc.y);
                acc.z = fmaf(w0, v0.z, acc.z); acc.w = fmaf(w0, v0.w, acc.w);
                acc.x = fmaf(w1, v1.x, acc.x); acc.y = fmaf(w1, v1.y, acc.y);
                acc.z = fmaf(w1, v1.z, acc.z); acc.w = fmaf(w1, v1.w, acc.w);
            }
            if (e < end) {
                int2 r0 = __ldg(&csr[e]);
                float4 v0 = __ldg((const float4*)(S + (size_t)r0.x * 128) + lane);
                float w0 = __int_as_float(r0.y);
                acc.x = fmaf(w0, v0.x, acc.x); acc.y = fmaf(w0, v0.y, acc.y);
                acc.z = fmaf(w0, v0.z, acc.z); acc.w = fmaf(w0, v0.w, acc.w);
            }
            acc.x = fmaxf(acc.x, 0.f); acc.y = fmaxf(acc.y, 0.f);
            acc.z = fmaxf(acc.z, 0.f); acc.w = fmaxf(acc.w, 0.f);
            uint2 h, l;
            h.x = pack2bf(acc.x, acc.y);  h.y = pack2bf(acc.z, acc.w);
            l.x = pack2bf(bfres(acc.x), bfres(acc.y));
            l.y = pack2bf(bfres(acc.z), bfres(acc.w));
            uint32_t off = (lane >> 3) * ACH + lnode * ROWB + (lane & 7) * 8;
            *(uint2*)(smem + off) = h;
            *(uint2*)(smem + A_LO + off) = l;
        } else {
            float2 acc = __ldg((const float2*)bias + lane);
            int e = start;
            for (; e + 1 < end; e += 2) {
                int2 r0 = __ldg(&csr[e]);
                int2 r1 = __ldg(&csr[e + 1]);
                float2 v0 = __ldg((const float2*)(S + (size_t)r0.x * 64) + lane);
                float2 v1 = __ldg((const float2*)(S + (size_t)r1.x * 64) + lane);
                float w0 = __int_as_float(r0.y), w1 = __int_as_float(r1.y);
                acc.x = fmaf(w0, v0.x, acc.x); acc.y = fmaf(w0, v0.y, acc.y);
                acc.x = fmaf(w1, v1.x, acc.x); acc.y = fmaf(w1, v1.y, acc.y);
            }
            if (e < end) {
                int2 r0 = __ldg(&csr[e]);
                float2 v0 = __ldg((const float2*)(S + (size_t)r0.x * 64) + lane);
                float w0 = __int_as_float(r0.y);
                acc.x = fmaf(w0, v0.x, acc.x); acc.y = fmaf(w0, v0.y, acc.y);
            }
            acc.x = fmaxf(acc.x, 0.f); acc.y = fmaxf(acc.y, 0.f);
            uint32_t off = (lane >> 4) * ACH + lnode * ROWB + (lane & 15) * 4;
            *(unsigned*)(smem + off) = pack2bf(acc.x, acc.y);
            *(unsigned*)(smem + A_LO + off) = pack2bf(bfres(acc.x), bfres(acc.y));
        }
    }
    CP_WAIT0();
    __syncthreads();

    // ---- Phase 2: GEMM (warp grid 4m x 8n; warp tile 32 x 8) ----
    const int wm = wid & 3, wn = wid >> 2;
    const int lrow = lane & 7, lmat = lane >> 3;
    const int bl16 = lane & 15;
    float acc[2][4];
#pragma unroll
    for (int mf = 0; mf < 2; mf++)
#pragma unroll
        for (int j = 0; j < 4; j++) acc[mf][j] = 0.f;

#pragma unroll
    for (int ch = 0; ch < NCH; ch++) {
        const uint32_t aHi = sb + ch * ACH;
        const uint32_t aLo = sb + A_LO + ch * ACH;
        const uint32_t bHi = sb + B_HI + ch * BCH;
        const uint32_t bLo = sb + B_LO + ch * BCH;
#pragma unroll
        for (int ks = 0; ks < 2; ks++) {
            uint32_t boff = (wn * 8 + (bl16 & 7)) * ROWB + (2 * ks + (bl16 >> 3)) * 16;
            uint32_t bh[2], bl[2];
            ldsm2(bh[0], bh[1], bHi + boff);
            ldsm2(bl[0], bl[1], bLo + boff);
#pragma unroll
            for (int mf = 0; mf < 2; mf++) {
                int arow = wm * 32 + mf * 16 + lrow + (lmat & 1) * 8;
                uint32_t aoff = arow * ROWB + (2 * ks + (lmat >> 1)) * 16;
                uint32_t ah[4], al[4];
                ldsm4(ah[0], ah[1], ah[2], ah[3], aHi + aoff);
                ldsm4(al[0], al[1], al[2], al[3], aLo + aoff);
                mma_bf16(acc[mf], ah, bh);
                mma_bf16(acc[mf], ah, bl);
                mma_bf16(acc[mf], al, bh);
            }
        }
    }

    // Epilogue: write next support (fp32)
    const int r0 = lane >> 2;
    const int c0 = (lane & 3) * 2;
#pragma unroll
    for (int mf = 0; mf < 2; mf++) {
#pragma unroll
        for (int half = 0; half < 2; half++) {
            int row = bm + wm * 32 + mf * 16 + r0 + half * 8;
            if (row < M) {
                float2 v = make_float2(acc[mf][half * 2], acc[mf][half * 2 + 1]);
                *(float2*)&Sout[(size_t)row * N_OUT + wn * 8 + c0] = v;
            }
        }
    }
}

// ---------------------------------------------------------------------------
// CSR pull-mode SpMM (final layer): out = adj@S + b3
// ---------------------------------------------------------------------------
__global__ void spmm_final_kernel(const float* __restrict__ S, const int2* __restrict__ csr,
                                  const int* __restrict__ rowptr, const float* __restrict__ bias,
                                  float* __restrict__ out) {
    int warp = (blockIdx.x * blockDim.x + threadIdx.x) >> 5;
    int lane = threadIdx.x & 31;
    if (warp >= NN) return;
    int start = __ldg(&rowptr[warp]);
    int end = __ldg(&rowptr[warp + 1]);
    float2 acc = __ldg((const float2*)bias + lane);
    int e = start;
    for (; e + 1 < end; e += 2) {
        int2 r0 = __ldg(&csr[e]);
        int2 r1 = __ldg(&csr[e + 1]);
        float2 v0 = __ldg((const float2*)(S + (size_t)r0.x * 64) + lane);
        float2 v1 = __ldg((const float2*)(S + (size_t)r1.x * 64) + lane);
        float w0 = __int_as_float(r0.y), w1 = __int_as_float(r1.y);
        acc.x = fmaf(w0, v0.x, acc.x); acc.y = fmaf(w0, v0.y, acc.y);
        acc.x = fmaf(w1, v1.x, acc.x); acc.y = fmaf(w1, v1.y, acc.y);
    }
    if (e < end) {
        int2 r0 = __ldg(&csr[e]);
        float2 v0 = __ldg((const float2*)(S + (size_t)r0.x * 64) + lane);
        float w0 = __int_as_float(r0.y);
        acc.x = fmaf(w0, v0.x, acc.x); acc.y = fmaf(w0, v0.y, acc.y);
    }
    *((float2*)(out + (size_t)warp * 64) + lane) = acc;
}

// ---------------------------------------------------------------------------
extern "C" void kernel_launch(void* const* d_in, const int* in_sizes, int n_in,
                              void* d_out, int out_size) {
    const float* x    = (const float*)d_in[0];
    const int*   esrc = (const int*)d_in[1];
    const int*   edst = (const int*)d_in[2];
    const float* ew   = (const float*)d_in[3];
    const float* W1   = (const float*)d_in[4];
    const float* b1   = (const float*)d_in[5];
    const float* W2   = (const float*)d_in[6];
    const float* b2   = (const float*)d_in[7];
    const float* W3   = (const float*)d_in[8];
    const float* b3   = (const float*)d_in[9];
    float* out = (float*)d_out;

    float *S, *S2, *S3;
    __nv_bfloat16 *WH, *WL;
    int *cnt, *pre, *bsum, *btop, *rowptr, *cursor;
    int2* csr;
    cudaGetSymbolAddress((void**)&S, g_S);
    cudaGetSymbolAddress((void**)&S2, g_S2);
    cudaGetSymbolAddress((void**)&S3, g_S3);
    cudaGetSymbolAddress((void**)&WH, g_WH);
    cudaGetSymbolAddress((void**)&WL, g_WL);
    cudaGetSymbolAddress((void**)&cnt, g_cnt);
    cudaGetSymbolAddress((void**)&pre, g_pre);
    cudaGetSymbolAddress((void**)&bsum, g_bsum);
    cudaGetSymbolAddress((void**)&btop, g_btop);
    cudaGetSymbolAddress((void**)&rowptr, g_rowptr);
    cudaGetSymbolAddress((void**)&cursor, g_cursor);
    cudaGetSymbolAddress((void**)&csr, g_csr);

    static cudaStream_t s2strm = nullptr;
    static cudaEvent_t evFork = nullptr, evJoin = nullptr;
    if (s2strm == nullptr) {
        cudaStreamCreateWithFlags(&s2strm, cudaStreamNonBlocking);
        cudaEventCreateWithFlags(&evFork, cudaEventDisableTiming);
        cudaEventCreateWithFlags(&evJoin, cudaEventDisableTiming);
    }

    const int E = NE, M = NN;
    const int gx = (M + 127) / 128;   // 782

    cudaFuncSetAttribute(gemm_mma_kernel<128, 256>, cudaFuncAttributeMaxDynamicSharedMemorySize, 81920);
    cudaFuncSetAttribute(fused_spmm_gemm_kernel<128, 64>, cudaFuncAttributeMaxDynamicSharedMemorySize, 122880);
    cudaFuncSetAttribute(fused_spmm_gemm_kernel<64, 64>, cudaFuncAttributeMaxDynamicSharedMemorySize, 61440);

    // ----- Fork: CSR build + W2/W3 splits on side stream -----
    cudaEventRecord(evFork, 0);
    cudaStreamWaitEvent(s2strm, evFork, 0);
    zero_kernel<<<(NN + 511) / 512, 512, 0, s2strm>>>(cnt, NN);
    count_kernel<<<(E + 511) / 512, 512, 0, s2strm>>>(edst, cnt, E);
    scan_block_kernel<<<NBLK_SCAN, 1024, 0, s2strm>>>(cnt, pre, bsum, NN);
    scan_block_kernel<<<1, 1024, 0, s2strm>>>(bsum, btop, nullptr, NBLK_SCAN);
    add_offsets_kernel<<<(NN + 511) / 512, 512, 0, s2strm>>>(pre, btop, rowptr, cursor, NN);
    scatter_kernel<<<(E + 511) / 512, 512, 0, s2strm>>>(esrc, edst, ew, cursor, csr, E);
    wsplit_kernel<<<(128 * 64 + 255) / 256, 256, 0, s2strm>>>(W2, WH + 32768, WL + 32768, 128, 64);
    wsplit_kernel<<<(64 * 64 + 255) / 256, 256, 0, s2strm>>>(W3, WH + 40960, WL + 40960, 64, 64);
    cudaEventRecord(evJoin, s2strm);

    // ----- Main: W1 split + GEMM1 (fp32 A, in-kernel convert) -----
    wsplit_kernel<<<(256 * 128 + 255) / 256, 256>>>(W1, WH, WL, 256, 128);
    gemm_mma_kernel<128, 256><<<gx, 256, 81920>>>(x, WH, WL, S, M);

    // ----- Join, then fused layers -----
    cudaStreamWaitEvent(0, evJoin, 0);
    fused_spmm_gemm_kernel<128, 64><<<gx, 1024, 122880>>>(S, csr, rowptr, b1,
                                                          WH + 32768, WL + 32768, S2, M);
    fused_spmm_gemm_kernel<64, 64><<<gx, 1024, 61440>>>(S2, csr, rowptr, b2,
                                                        WH + 40960, WL + 40960, S3, M);
    spmm_final_kernel<<<(NN + 7) / 8, 256>>>(S3, csr, rowptr, b3, out);
}

// round 9
// speedup vs baseline: 1.3825x; 1.3825x over previous
#include <cuda_runtime.h>
#include <cuda_bf16.h>
#include <cuda_fp16.h>
#include <cstdint>

#define NN 100000
#define NE 1600000
#define NBLK_SCAN 98   // ceil(100000/1024)

// ---------------------------------------------------------------------------
// Scratch (static device arrays; allocation-free per harness rules).
// ---------------------------------------------------------------------------
__device__ __half        g_S1h[(size_t)NN * 128]; // layer-1 support (fp16)
__device__ __half        g_S2h[(size_t)NN * 64];  // layer-2 support (fp16)
__device__ float         g_S3[(size_t)NN * 64];   // layer-3 support (fp32)
__device__ __nv_bfloat16 g_H[(size_t)NN * 128];   // hi-plane of next GEMM A operand
__device__ __nv_bfloat16 g_L[(size_t)NN * 128];   // lo-plane of next GEMM A operand
__device__ __nv_bfloat16 g_WH[45056];             // weight hi planes (W1T|W2T|W3T)
__device__ __nv_bfloat16 g_WL[45056];             // weight lo planes
__device__ int   g_cnt[NN];
__device__ int   g_pre[NN];
__device__ int   g_bsum[1024];
__device__ int   g_btop[1024];
__device__ int   g_rowptr[NN + 1];
__device__ int   g_cursor[NN];
__device__ int2  g_csr[NE];

// ---------------------------------------------------------------------------
// Helpers
// ---------------------------------------------------------------------------
__device__ __forceinline__ uint32_t smem_u32(const void* p) {
    uint32_t a;
    asm("{ .reg .u64 t; cvta.to.shared.u64 t, %1; cvt.u32.u64 %0, t; }" : "=r"(a) : "l"(p));
    return a;
}
__device__ __forceinline__ void cp16(uint32_t s, const void* g, bool pred) {
    asm volatile("cp.async.cg.shared.global [%0], [%1], 16, %2;"
                 :: "r"(s), "l"(g), "r"(pred ? 16 : 0));
}
#define CP_COMMIT() asm volatile("cp.async.commit_group;" ::: "memory")
#define CP_WAIT0()  asm volatile("cp.async.wait_group 0;" ::: "memory")
#define CP_WAIT1()  asm volatile("cp.async.wait_group 1;" ::: "memory")

__device__ __forceinline__ void ldsm4(uint32_t& r0, uint32_t& r1, uint32_t& r2, uint32_t& r3,
                                      uint32_t addr) {
    asm volatile("ldmatrix.sync.aligned.m8n8.x4.shared.b16 {%0,%1,%2,%3}, [%4];"
                 : "=r"(r0), "=r"(r1), "=r"(r2), "=r"(r3) : "r"(addr));
}
__device__ __forceinline__ void mma_bf16(float* d, const uint32_t* a, const uint32_t* b) {
    asm volatile(
        "mma.sync.aligned.m16n8k16.row.col.f32.bf16.bf16.f32 "
        "{%0,%1,%2,%3}, {%4,%5,%6,%7}, {%8,%9}, {%0,%1,%2,%3};"
        : "+f"(d[0]), "+f"(d[1]), "+f"(d[2]), "+f"(d[3])
        : "r"(a[0]), "r"(a[1]), "r"(a[2]), "r"(a[3]), "r"(b[0]), "r"(b[1]));
}
__device__ __forceinline__ unsigned pack2bf(float a, float b) {
    __nv_bfloat162 t = make_bfloat162(__float2bfloat16_rn(a), __float2bfloat16_rn(b));
    return *reinterpret_cast<unsigned*>(&t);
}
__device__ __forceinline__ float bfres(float v) {
    return v - __bfloat162float(__float2bfloat16_rn(v));
}

// ---------------------------------------------------------------------------
// CSR build kernels (known good)
// ---------------------------------------------------------------------------
__global__ void zero_kernel(int* __restrict__ p, int n) {
    int i = blockIdx.x * blockDim.x + threadIdx.x;
    if (i < n) p[i] = 0;
}
__global__ void count_kernel(const int* __restrict__ dst, int* __restrict__ cnt, int E) {
    int e = blockIdx.x * blockDim.x + threadIdx.x;
    if (e < E) atomicAdd(&cnt[__ldg(&dst[e])], 1);
}
__global__ void scan_block_kernel(const int* __restrict__ in, int* __restrict__ outx,
                                  int* __restrict__ sums, int n) {
    __shared__ int s[2][1024];
    int tid = threadIdx.x;
    int i = blockIdx.x * 1024 + tid;
    int v = (i < n) ? in[i] : 0;
    int pin = 0;
    s[0][tid] = v;
    __syncthreads();
#pragma unroll
    for (int off = 1; off < 1024; off <<= 1) {
        int t = s[pin][tid] + ((tid >= off) ? s[pin][tid - off] : 0);
        s[pin ^ 1][tid] = t;
        pin ^= 1;
        __syncthreads();
    }
    if (i < n) outx[i] = s[pin][tid] - v;
    if (sums != nullptr && tid == 1023) sums[blockIdx.x] = s[pin][1023];
}
__global__ void add_offsets_kernel(const int* __restrict__ pre, const int* __restrict__ top,
                                   int* __restrict__ rowptr, int* __restrict__ cursor, int n) {
    int i = blockIdx.x * blockDim.x + threadIdx.x;
    if (i < n) {
        int v = pre[i] + __ldg(&top[i >> 10]);
        rowptr[i] = v;
        cursor[i] = v;
    }
    if (i == 0) rowptr[n] = NE;
}
__global__ void scatter_kernel(const int* __restrict__ src, const int* __restrict__ dst,
                               const float* __restrict__ w, int* __restrict__ cursor,
                               int2* __restrict__ csr, int E) {
    int e = blockIdx.x * blockDim.x + threadIdx.x;
    if (e >= E) return;
    int d = __ldg(&dst[e]);
    int pos = atomicAdd(&cursor[d], 1);
    csr[pos] = make_int2(__ldg(&src[e]), __float_as_int(__ldg(&w[e])));
}

// W[K,N] row-major -> planes [N,K] k-major
__global__ void wsplit_kernel(const float* __restrict__ W, __nv_bfloat16* __restrict__ hi,
                              __nv_bfloat16* __restrict__ lo, int K, int N) {
    int i = blockIdx.x * blockDim.x + threadIdx.x;
    if (i >= K * N) return;
    int n = i / K, k = i % K;
    float v = __ldg(&W[(size_t)k * N + n]);
    hi[(size_t)n * K + k] = __float2bfloat16_rn(v);
    lo[(size_t)n * K + k] = __float2bfloat16_rn(bfres(v));
}

// ---------------------------------------------------------------------------
// HMMA bf16-split GEMM: C[M,N_OUT] = A[M,K] @ (Bhi+Blo)[N_OUT,K]^T
// CONV=true : A fp32, converted in-kernel; LDG prefetch pipelined across compute.
// CONV=false: A pre-split bf16 planes via cp.async (R6 scheme).
// OUT_HALF: write C as fp16x2 instead of fp32.
// ---------------------------------------------------------------------------
template <int N_OUT, int K_TOTAL, bool CONV, bool OUT_HALF>
__global__ __launch_bounds__(256, 2)
void gemm_mma_kernel(const float* __restrict__ Af,
                     const __nv_bfloat16* __restrict__ Ahi, const __nv_bfloat16* __restrict__ Alo,
                     const __nv_bfloat16* __restrict__ Bhi, const __nv_bfloat16* __restrict__ Blo,
                     void* __restrict__ Cout, int M) {
    constexpr int NCH = K_TOTAL / 32;
    constexpr int ROWB = 80;
    constexpr int AT = 128 * ROWB;
    constexpr int BT = N_OUT * ROWB;
    constexpr int STAGE = 2 * AT + 2 * BT;
    constexpr int WN = N_OUT / 4;
    constexpr int NF = WN / 8;

    extern __shared__ char smem[];
    const uint32_t sb = smem_u32(smem);
    const int tid = threadIdx.x;
    const int wid = tid >> 5, lane = tid & 31;
    const int wm = wid & 1, wn = wid >> 1;
    const int bm = blockIdx.x * 128;
    const int lrow = lane & 7;
    const int lmat = lane >> 3;

    float acc[4][NF][4];
#pragma unroll
    for (int mf = 0; mf < 4; mf++)
#pragma unroll
        for (int nf = 0; nf < NF; nf++)
#pragma unroll
            for (int j = 0; j < 4; j++) acc[mf][nf][j] = 0.f;

    float4 pa[4];  // CONV prefetch registers

    auto ldgA = [&](int ch) {
#pragma unroll
        for (int i = 0; i < 4; i++) {
            int idx = tid + i * 256;
            int row = idx >> 3, seg = idx & 7;
            pa[i] = make_float4(0.f, 0.f, 0.f, 0.f);
            if (bm + row < M)
                pa[i] = __ldg((const float4*)&Af[(size_t)(bm + row) * K_TOTAL + ch * 32 + seg * 4]);
        }
    };
    auto stsA = [&](int st) {
#pragma unroll
        for (int i = 0; i < 4; i++) {
            int idx = tid + i * 256;
            int row = idx >> 3, seg = idx & 7;
            float4 v = pa[i];
            uint2 h, l;
            h.x = pack2bf(v.x, v.y);  h.y = pack2bf(v.z, v.w);
            l.x = pack2bf(bfres(v.x), bfres(v.y));
            l.y = pack2bf(bfres(v.z), bfres(v.w));
            uint32_t off = row * ROWB + seg * 8;
            *(uint2*)(smem + st * STAGE + off) = h;
            *(uint2*)(smem + st * STAGE + AT + off) = l;
        }
    };
    auto loadA_cp = [&](int ch, int st) {
        const uint32_t base = sb + st * STAGE;
#pragma unroll
        for (int i = 0; i < 2; i++) {
            int idx = tid + i * 256;
            int row = idx >> 2, seg = idx & 3;
            bool p = (bm + row) < M;
            size_t g = (size_t)(bm + row) * K_TOTAL + ch * 32 + seg * 8;
            cp16(base + row * ROWB + seg * 16, Ahi + g, p);
            cp16(base + AT + row * ROWB + seg * 16, Alo + g, p);
        }
    };
    auto loadB = [&](int ch, int st) {
        const uint32_t base = sb + st * STAGE;
#pragma unroll
        for (int i = 0; i < (N_OUT * 4) / 256; i++) {
            int idx = tid + i * 256;
            int row = idx >> 2, seg = idx & 3;
            size_t g = (size_t)row * K_TOTAL + ch * 32 + seg * 8;
            cp16(base + 2 * AT + row * ROWB + seg * 16, Bhi + g, true);
            cp16(base + 2 * AT + BT + row * ROWB + seg * 16, Blo + g, true);
        }
        CP_COMMIT();
    };
    auto compute = [&](int st) {
        const uint32_t base = sb + st * STAGE;
        const uint32_t aHi = base, aLo = base + AT;
        const uint32_t bHi = base + 2 * AT, bLo = base + 2 * AT + BT;
#pragma unroll
        for (int ks = 0; ks < 2; ks++) {
            const int seg = 2 * ks + (lmat >> 1);
            uint32_t bh[NF][2], bl[NF][2];
#pragma unroll
            for (int p = 0; p < NF / 2; p++) {
                int nrow = wn * WN + p * 16 + lrow + (lmat & 1) * 8;
                uint32_t off = nrow * ROWB + seg * 16;
                uint32_t r0, r1, r2, r3;
                ldsm4(r0, r1, r2, r3, bHi + off);
                bh[2 * p][0] = r0; bh[2 * p + 1][0] = r1;
                bh[2 * p][1] = r2; bh[2 * p + 1][1] = r3;
                ldsm4(r0, r1, r2, r3, bLo + off);
                bl[2 * p][0] = r0; bl[2 * p + 1][0] = r1;
                bl[2 * p][1] = r2; bl[2 * p + 1][1] = r3;
            }
#pragma unroll
            for (int mf = 0; mf < 4; mf++) {
                int arow = wm * 64 + mf * 16 + lrow + (lmat & 1) * 8;
                uint32_t off = arow * ROWB + seg * 16;
                uint32_t ah[4], al[4];
                ldsm4(ah[0], ah[1], ah[2], ah[3], aHi + off);
                ldsm4(al[0], al[1], al[2], al[3], aLo + off);
#pragma unroll
                for (int nf = 0; nf < NF; nf++) {
                    mma_bf16(acc[mf][nf], ah, bh[nf]);
                    mma_bf16(acc[mf][nf], ah, bl[nf]);
                    mma_bf16(acc[mf][nf], al, bh[nf]);
                }
            }
        }
    };

    if (CONV) {
        // Pipelined: LDG(c+1) issued before compute(c); STS after.
        ldgA(0);
        stsA(0);
        loadB(0, 0);
        CP_WAIT0();
        __syncthreads();
        for (int c = 0; c < NCH; c++) {
            bool more = (c + 1) < NCH;
            if (more) { ldgA(c + 1); loadB(c + 1, (c + 1) & 1); }
            compute(c & 1);
            if (more) {
                stsA((c + 1) & 1);
                CP_WAIT0();
                __syncthreads();
            }
        }
    } else {
        loadA_cp(0, 0);
        loadB(0, 0);
        for (int c = 0; c < NCH; c++) {
            if (c + 1 < NCH) {
                loadA_cp(c + 1, (c + 1) & 1);
                loadB(c + 1, (c + 1) & 1);
                CP_WAIT1();
            } else {
                CP_WAIT0();
            }
            __syncthreads();
            compute(c & 1);
            __syncthreads();
        }
    }

    // Epilogue
    const int r0 = lane >> 2;
    const int c0 = (lane & 3) * 2;
#pragma unroll
    for (int mf = 0; mf < 4; mf++) {
        int row = bm + wm * 64 + mf * 16 + r0;
#pragma unroll
        for (int half = 0; half < 2; half++) {
            int rr = row + half * 8;
            if (rr < M) {
#pragma unroll
                for (int nf = 0; nf < NF; nf++) {
                    int col = wn * WN + nf * 8 + c0;
                    if (OUT_HALF) {
                        __half2 hv = __floats2half2_rn(acc[mf][nf][half * 2],
                                                       acc[mf][nf][half * 2 + 1]);
                        *(__half2*)&((__half*)Cout)[(size_t)rr * N_OUT + col] = hv;
                    } else {
                        float2 v = make_float2(acc[mf][nf][half * 2], acc[mf][nf][half * 2 + 1]);
                        *(float2*)&((float*)Cout)[(size_t)rr * N_OUT + col] = v;
                    }
                }
            }
        }
    }
}

// ---------------------------------------------------------------------------
// CSR pull-mode SpMM over fp16 support, fused bias+relu+hi/lo split output.
// One warp per destination node; 2-way unrolled edge loop.
// ---------------------------------------------------------------------------
template <int D>
__global__ void spmm_h_kernel(const __half* __restrict__ S, const int2* __restrict__ csr,
                              const int* __restrict__ rowptr, const float* __restrict__ bias,
                              __nv_bfloat16* __restrict__ outh, __nv_bfloat16* __restrict__ outl) {
    int warp = (blockIdx.x * blockDim.x + threadIdx.x) >> 5;
    int lane = threadIdx.x & 31;
    if (warp >= NN) return;
    int start = __ldg(&rowptr[warp]);
    int end = __ldg(&rowptr[warp + 1]);

    if (D == 128) {
        float4 acc = __ldg((const float4*)bias + lane);
        int e = start;
        for (; e + 1 < end; e += 2) {
            int2 r0 = __ldg(&csr[e]);
            int2 r1 = __ldg(&csr[e + 1]);
            uint2 q0 = __ldg((const uint2*)(S + (size_t)r0.x * 128) + lane);
            uint2 q1 = __ldg((const uint2*)(S + (size_t)r1.x * 128) + lane);
            float w0 = __int_as_float(r0.y), w1 = __int_as_float(r1.y);
            float2 a0 = __half22float2(*(__half2*)&q0.x);
            float2 b0 = __half22float2(*(__half2*)&q0.y);
            float2 a1 = __half22float2(*(__half2*)&q1.x);
            float2 b1 = __half22float2(*(__half2*)&q1.y);
            acc.x = fmaf(w0, a0.x, acc.x); acc.y = fmaf(w0, a0.y, acc.y);
            acc.z = fmaf(w0, b0.x, acc.z); acc.w = fmaf(w0, b0.y, acc.w);
            acc.x = fmaf(w1, a1.x, acc.x); acc.y = fmaf(w1, a1.y, acc.y);
            acc.z = fmaf(w1, b1.x, acc.z); acc.w = fmaf(w1, b1.y, acc.w);
        }
        if (e < end) {
            int2 r0 = __ldg(&csr[e]);
            uint2 q0 = __ldg((const uint2*)(S + (size_t)r0.x * 128) + lane);
            float w0 = __int_as_float(r0.y);
            float2 a0 = __half22float2(*(__half2*)&q0.x);
            float2 b0 = __half22float2(*(__half2*)&q0.y);
            acc.x = fmaf(w0, a0.x, acc.x); acc.y = fmaf(w0, a0.y, acc.y);
            acc.z = fmaf(w0, b0.x, acc.z); acc.w = fmaf(w0, b0.y, acc.w);
        }
        acc.x = fmaxf(acc.x, 0.f); acc.y = fmaxf(acc.y, 0.f);
        acc.z = fmaxf(acc.z, 0.f); acc.w = fmaxf(acc.w, 0.f);
        uint2 h, l;
        h.x = pack2bf(acc.x, acc.y);  h.y = pack2bf(acc.z, acc.w);
        l.x = pack2bf(bfres(acc.x), bfres(acc.y));
        l.y = pack2bf(bfres(acc.z), bfres(acc.w));
        ((uint2*)(outh + (size_t)warp * 128))[lane] = h;
        ((uint2*)(outl + (size_t)warp * 128))[lane] = l;
    } else {
        float2 acc = __ldg((const float2*)bias + lane);
        int e = start;
        for (; e + 1 < end; e += 2) {
            int2 r0 = __ldg(&csr[e]);
            int2 r1 = __ldg(&csr[e + 1]);
            unsigned q0 = __ldg((const unsigned*)(S + (size_t)r0.x * 64) + lane);
            unsigned q1 = __ldg((const unsigned*)(S + (size_t)r1.x * 64) + lane);
            float w0 = __int_as_float(r0.y), w1 = __int_as_float(r1.y);
            float2 v0 = __half22float2(*(__half2*)&q0);
            float2 v1 = __half22float2(*(__half2*)&q1);
            acc.x = fmaf(w0, v0.x, acc.x); acc.y = fmaf(w0, v0.y, acc.y);
            acc.x = fmaf(w1, v1.x, acc.x); acc.y = fmaf(w1, v1.y, acc.y);
        }
        if (e < end) {
            int2 r0 = __ldg(&csr[e]);
            unsigned q0 = __ldg((const unsigned*)(S + (size_t)r0.x * 64) + lane);
            float w0 = __int_as_float(r0.y);
            float2 v0 = __half22float2(*(__half2*)&q0);
            acc.x = fmaf(w0, v0.x, acc.x); acc.y = fmaf(w0, v0.y, acc.y);
        }
        acc.x = fmaxf(acc.x, 0.f); acc.y = fmaxf(acc.y, 0.f);
        ((unsigned*)(outh + (size_t)warp * 64))[lane] = pack2bf(acc.x, acc.y);
        ((unsigned*)(outl + (size_t)warp * 64))[lane] = pack2bf(bfres(acc.x), bfres(acc.y));
    }
}

// ---------------------------------------------------------------------------
// Final-layer SpMM (fp32 in, fp32 out, bias, no relu)
// ---------------------------------------------------------------------------
__global__ void spmm_final_kernel(const float* __restrict__ S, const int2* __restrict__ csr,
                                  const int* __restrict__ rowptr, const float* __restrict__ bias,
                                  float* __restrict__ out) {
    int warp = (blockIdx.x * blockDim.x + threadIdx.x) >> 5;
    int lane = threadIdx.x & 31;
    if (warp >= NN) return;
    int start = __ldg(&rowptr[warp]);
    int end = __ldg(&rowptr[warp + 1]);
    float2 acc = __ldg((const float2*)bias + lane);
    int e = start;
    for (; e + 1 < end; e += 2) {
        int2 r0 = __ldg(&csr[e]);
        int2 r1 = __ldg(&csr[e + 1]);
        float2 v0 = __ldg((const float2*)(S + (size_t)r0.x * 64) + lane);
        float2 v1 = __ldg((const float2*)(S + (size_t)r1.x * 64) + lane);
        float w0 = __int_as_float(r0.y), w1 = __int_as_float(r1.y);
        acc.x = fmaf(w0, v0.x, acc.x); acc.y = fmaf(w0, v0.y, acc.y);
        acc.x = fmaf(w1, v1.x, acc.x); acc.y = fmaf(w1, v1.y, acc.y);
    }
    if (e < end) {
        int2 r0 = __ldg(&csr[e]);
        float2 v0 = __ldg((const float2*)(S + (size_t)r0.x * 64) + lane);
        float w0 = __int_as_float(r0.y);
        acc.x = fmaf(w0, v0.x, acc.x); acc.y = fmaf(w0, v0.y, acc.y);
    }
    *((float2*)(out + (size_t)warp * 64) + lane) = acc;
}

// ---------------------------------------------------------------------------
extern "C" void kernel_launch(void* const* d_in, const int* in_sizes, int n_in,
                              void* d_out, int out_size) {
    const float* x    = (const float*)d_in[0];
    const int*   esrc = (const int*)d_in[1];
    const int*   edst = (const int*)d_in[2];
    const float* ew   = (const float*)d_in[3];
    const float* W1   = (const float*)d_in[4];
    const float* b1   = (const float*)d_in[5];
    const float* W2   = (const float*)d_in[6];
    const float* b2   = (const float*)d_in[7];
    const float* W3   = (const float*)d_in[8];
    const float* b3   = (const float*)d_in[9];
    float* out = (float*)d_out;

    __half *S1h, *S2h;
    float* S3;
    __nv_bfloat16 *H, *L, *WH, *WL;
    int *cnt, *pre, *bsum, *btop, *rowptr, *cursor;
    int2* csr;
    cudaGetSymbolAddress((void**)&S1h, g_S1h);
    cudaGetSymbolAddress((void**)&S2h, g_S2h);
    cudaGetSymbolAddress((void**)&S3, g_S3);
    cudaGetSymbolAddress((void**)&H, g_H);
    cudaGetSymbolAddress((void**)&L, g_L);
    cudaGetSymbolAddress((void**)&WH, g_WH);
    cudaGetSymbolAddress((void**)&WL, g_WL);
    cudaGetSymbolAddress((void**)&cnt, g_cnt);
    cudaGetSymbolAddress((void**)&pre, g_pre);
    cudaGetSymbolAddress((void**)&bsum, g_bsum);
    cudaGetSymbolAddress((void**)&btop, g_btop);
    cudaGetSymbolAddress((void**)&rowptr, g_rowptr);
    cudaGetSymbolAddress((void**)&cursor, g_cursor);
    cudaGetSymbolAddress((void**)&csr, g_csr);

    static cudaStream_t s2strm = nullptr;
    static cudaEvent_t evFork = nullptr, evJoin = nullptr;
    if (s2strm == nullptr) {
        cudaStreamCreateWithFlags(&s2strm, cudaStreamNonBlocking);
        cudaEventCreateWithFlags(&evFork, cudaEventDisableTiming);
        cudaEventCreateWithFlags(&evJoin, cudaEventDisableTiming);
    }

    const int E = NE, M = NN;
    const int gx = (M + 127) / 128;

    cudaFuncSetAttribute(gemm_mma_kernel<128, 256, true, true>,
                         cudaFuncAttributeMaxDynamicSharedMemorySize, 81920);
    cudaFuncSetAttribute(gemm_mma_kernel<64, 128, false, true>,
                         cudaFuncAttributeMaxDynamicSharedMemorySize, 61440);
    cudaFuncSetAttribute(gemm_mma_kernel<64, 64, false, false>,
                         cudaFuncAttributeMaxDynamicSharedMemorySize, 61440);

    // ----- Fork: CSR build + W2/W3 splits on side stream -----
    cudaEventRecord(evFork, 0);
    cudaStreamWaitEvent(s2strm, evFork, 0);
    zero_kernel<<<(NN + 511) / 512, 512, 0, s2strm>>>(cnt, NN);
    count_kernel<<<(E + 511) / 512, 512, 0, s2strm>>>(edst, cnt, E);
    scan_block_kernel<<<NBLK_SCAN, 1024, 0, s2strm>>>(cnt, pre, bsum, NN);
    scan_block_kernel<<<1, 1024, 0, s2strm>>>(bsum, btop, nullptr, NBLK_SCAN);
    add_offsets_kernel<<<(NN + 511) / 512, 512, 0, s2strm>>>(pre, btop, rowptr, cursor, NN);
    scatter_kernel<<<(E + 511) / 512, 512, 0, s2strm>>>(esrc, edst, ew, cursor, csr, E);
    wsplit_kernel<<<(128 * 64 + 255) / 256, 256, 0, s2strm>>>(W2, WH + 32768, WL + 32768, 128, 64);
    wsplit_kernel<<<(64 * 64 + 255) / 256, 256, 0, s2strm>>>(W3, WH + 40960, WL + 40960, 64, 64);
    cudaEventRecord(evJoin, s2strm);

    // ----- Main: W1 split + GEMM1 (fp32 A, in-kernel convert; fp16 out) -----
    wsplit_kernel<<<(256 * 128 + 255) / 256, 256>>>(W1, WH, WL, 256, 128);
    gemm_mma_kernel<128, 256, true, true><<<gx, 256, 81920>>>(x, nullptr, nullptr, WH, WL, S1h, M);

    // ----- Join, then Layer 1 SpMM (fp16 gather) -----
    cudaStreamWaitEvent(0, evJoin, 0);
    spmm_h_kernel<128><<<(NN + 7) / 8, 256>>>(S1h, csr, rowptr, b1, H, L);

    // ----- Layer 2 (fp16 out / fp16 gather) -----
    gemm_mma_kernel<64, 128, false, true><<<gx, 256, 61440>>>(nullptr, H, L,
                                                              WH + 32768, WL + 32768, S2h, M);
    spmm_h_kernel<64><<<(NN + 7) / 8, 256>>>(S2h, csr, rowptr, b2, H, L);

    // ----- Layer 3 (fp32 throughout) -----
    gemm_mma_kernel<64, 64, false, false><<<gx, 256, 61440>>>(nullptr, H, L,
                                                              WH + 40960, WL + 40960, S3, M);
    spmm_final_kernel<<<(NN + 7) / 8, 256>>>(S3, csr, rowptr, b3, out);
}

// round 11
// speedup vs baseline: 1.4995x; 1.0846x over previous
#include <cuda_runtime.h>
#include <cuda_bf16.h>
#include <cuda_fp16.h>
#include <cstdint>

#define NN 100000
#define NE 1600000
#define NBLK_SCAN 98   // ceil(100000/1024)

// ---------------------------------------------------------------------------
// Scratch (static device arrays; allocation-free per harness rules).
// ---------------------------------------------------------------------------
__device__ __half        g_S1h[(size_t)NN * 128]; // layer-1 support (fp16)
__device__ __half        g_A1h[(size_t)NN * 128]; // layer-1 activation (fp16)
__device__ __half        g_S2h[(size_t)NN * 64];  // layer-2 support (fp16)
__device__ __half        g_A2h[(size_t)NN * 64];  // layer-2 activation (fp16)
__device__ __half        g_S3h[(size_t)NN * 64];  // layer-3 support (fp16)
__device__ __nv_bfloat16 g_WH[45056];             // weight hi planes (W1T|W2T|W3T)
__device__ __nv_bfloat16 g_WL[45056];             // weight lo planes
__device__ int   g_cnt[NN];
__device__ int   g_pre[NN];
__device__ int   g_bsum[1024];
__device__ int   g_btop[1024];
__device__ int   g_rowptr[NN + 1];
__device__ int   g_cursor[NN];
__device__ int2  g_csr[NE];

// ---------------------------------------------------------------------------
// Helpers
// ---------------------------------------------------------------------------
__device__ __forceinline__ uint32_t smem_u32(const void* p) {
    uint32_t a;
    asm("{ .reg .u64 t; cvta.to.shared.u64 t, %1; cvt.u32.u64 %0, t; }" : "=r"(a) : "l"(p));
    return a;
}
__device__ __forceinline__ void cp16(uint32_t s, const void* g, bool pred) {
    asm volatile("cp.async.cg.shared.global [%0], [%1], 16, %2;"
                 :: "r"(s), "l"(g), "r"(pred ? 16 : 0));
}
#define CP_COMMIT() asm volatile("cp.async.commit_group;" ::: "memory")
#define CP_WAIT0()  asm volatile("cp.async.wait_group 0;" ::: "memory")

__device__ __forceinline__ void ldsm4(uint32_t& r0, uint32_t& r1, uint32_t& r2, uint32_t& r3,
                                      uint32_t addr) {
    asm volatile("ldmatrix.sync.aligned.m8n8.x4.shared.b16 {%0,%1,%2,%3}, [%4];"
                 : "=r"(r0), "=r"(r1), "=r"(r2), "=r"(r3) : "r"(addr));
}
__device__ __forceinline__ void mma_bf16(float* d, const uint32_t* a, const uint32_t* b) {
    asm volatile(
        "mma.sync.aligned.m16n8k16.row.col.f32.bf16.bf16.f32 "
        "{%0,%1,%2,%3}, {%4,%5,%6,%7}, {%8,%9}, {%0,%1,%2,%3};"
        : "+f"(d[0]), "+f"(d[1]), "+f"(d[2]), "+f"(d[3])
        : "r"(a[0]), "r"(a[1]), "r"(a[2]), "r"(a[3]), "r"(b[0]), "r"(b[1]));
}
__device__ __forceinline__ unsigned pack2bf(float a, float b) {
    __nv_bfloat162 t = make_bfloat162(__float2bfloat16_rn(a), __float2bfloat16_rn(b));
    return *reinterpret_cast<unsigned*>(&t);
}
__device__ __forceinline__ float bfres(float v) {
    return v - __bfloat162float(__float2bfloat16_rn(v));
}

// ---------------------------------------------------------------------------
// CSR build kernels (known good)
// ---------------------------------------------------------------------------
__global__ void zero_kernel(int* __restrict__ p, int n) {
    int i = blockIdx.x * blockDim.x + threadIdx.x;
    if (i < n) p[i] = 0;
}
__global__ void count_kernel(const int* __restrict__ dst, int* __restrict__ cnt, int E) {
    int e = blockIdx.x * blockDim.x + threadIdx.x;
    if (e < E) atomicAdd(&cnt[__ldg(&dst[e])], 1);
}
__global__ void scan_block_kernel(const int* __restrict__ in, int* __restrict__ outx,
                                  int* __restrict__ sums, int n) {
    __shared__ int s[2][1024];
    int tid = threadIdx.x;
    int i = blockIdx.x * 1024 + tid;
    int v = (i < n) ? in[i] : 0;
    int pin = 0;
    s[0][tid] = v;
    __syncthreads();
#pragma unroll
    for (int off = 1; off < 1024; off <<= 1) {
        int t = s[pin][tid] + ((tid >= off) ? s[pin][tid - off] : 0);
        s[pin ^ 1][tid] = t;
        pin ^= 1;
        __syncthreads();
    }
    if (i < n) outx[i] = s[pin][tid] - v;
    if (sums != nullptr && tid == 1023) sums[blockIdx.x] = s[pin][1023];
}
__global__ void add_offsets_kernel(const int* __restrict__ pre, const int* __restrict__ top,
                                   int* __restrict__ rowptr, int* __restrict__ cursor, int n) {
    int i = blockIdx.x * blockDim.x + threadIdx.x;
    if (i < n) {
        int v = pre[i] + __ldg(&top[i >> 10]);
        rowptr[i] = v;
        cursor[i] = v;
    }
    if (i == 0) rowptr[n] = NE;
}
__global__ void scatter_kernel(const int* __restrict__ src, const int* __restrict__ dst,
                               const float* __restrict__ w, int* __restrict__ cursor,
                               int2* __restrict__ csr, int E) {
    int e = blockIdx.x * blockDim.x + threadIdx.x;
    if (e >= E) return;
    int d = __ldg(&dst[e]);
    int pos = atomicAdd(&cursor[d], 1);
    csr[pos] = make_int2(__ldg(&src[e]), __float_as_int(__ldg(&w[e])));
}

// W[K,N] row-major -> planes [N,K] k-major
__global__ void wsplit_kernel(const float* __restrict__ W, __nv_bfloat16* __restrict__ hi,
                              __nv_bfloat16* __restrict__ lo, int K, int N) {
    int i = blockIdx.x * blockDim.x + threadIdx.x;
    if (i >= K * N) return;
    int n = i / K, k = i % K;
    float v = __ldg(&W[(size_t)k * N + n]);
    hi[(size_t)n * K + k] = __float2bfloat16_rn(v);
    lo[(size_t)n * K + k] = __float2bfloat16_rn(bfres(v));
}

// ---------------------------------------------------------------------------
// HMMA bf16-split GEMM: C[M,N_OUT] = A[M,K] @ (Bhi+Blo)[N_OUT,K]^T
// AMODE 0: A fp32 -> hi/lo in regs.  AMODE 1: A fp16 -> hi/lo in regs (exact).
// Pipelined: LDG(c+1) before compute(c), STS after. Output fp16.
// ---------------------------------------------------------------------------
template <int N_OUT, int K_TOTAL, int AMODE>
__global__ __launch_bounds__(256, 2)
void gemm_mma_kernel(const void* __restrict__ Ain,
                     const __nv_bfloat16* __restrict__ Bhi, const __nv_bfloat16* __restrict__ Blo,
                     __half* __restrict__ Cout, int M) {
    constexpr int NCH = K_TOTAL / 32;
    constexpr int ROWB = 80;
    constexpr int AT = 128 * ROWB;
    constexpr int BT = N_OUT * ROWB;
    constexpr int STAGE = 2 * AT + 2 * BT;
    constexpr int WN = N_OUT / 4;
    constexpr int NF = WN / 8;

    extern __shared__ char smem[];
    const uint32_t sb = smem_u32(smem);
    const int tid = threadIdx.x;
    const int wid = tid >> 5, lane = tid & 31;
    const int wm = wid & 1, wn = wid >> 1;
    const int bm = blockIdx.x * 128;
    const int lrow = lane & 7;
    const int lmat = lane >> 3;

    float acc[4][NF][4];
#pragma unroll
    for (int mf = 0; mf < 4; mf++)
#pragma unroll
        for (int nf = 0; nf < NF; nf++)
#pragma unroll
            for (int j = 0; j < 4; j++) acc[mf][nf][j] = 0.f;

    float4 paf[4];   // AMODE 0 prefetch
    uint4 pah[2];    // AMODE 1 prefetch

    auto ldgA = [&](int ch) {
        if (AMODE == 0) {
            const float* Af = (const float*)Ain;
#pragma unroll
            for (int i = 0; i < 4; i++) {
                int idx = tid + i * 256;
                int row = idx >> 3, seg = idx & 7;
                paf[i] = make_float4(0.f, 0.f, 0.f, 0.f);
                if (bm + row < M)
                    paf[i] = __ldg((const float4*)&Af[(size_t)(bm + row) * K_TOTAL + ch * 32 + seg * 4]);
            }
        } else {
            const __half* Ah = (const __half*)Ain;
#pragma unroll
            for (int i = 0; i < 2; i++) {
                int idx = tid + i * 256;
                int row = idx >> 2, seg = idx & 3;
                pah[i] = make_uint4(0, 0, 0, 0);
                if (bm + row < M)
                    pah[i] = __ldg((const uint4*)(Ah + (size_t)(bm + row) * K_TOTAL + ch * 32 + seg * 8));
            }
        }
    };
    auto stsA = [&](int st) {
        if (AMODE == 0) {
#pragma unroll
            for (int i = 0; i < 4; i++) {
                int idx = tid + i * 256;
                int row = idx >> 3, seg = idx & 7;
                float4 v = paf[i];
                uint2 h, l;
                h.x = pack2bf(v.x, v.y);  h.y = pack2bf(v.z, v.w);
                l.x = pack2bf(bfres(v.x), bfres(v.y));
                l.y = pack2bf(bfres(v.z), bfres(v.w));
                uint32_t off = row * ROWB + seg * 8;
                *(uint2*)(smem + st * STAGE + off) = h;
                *(uint2*)(smem + st * STAGE + AT + off) = l;
            }
        } else {
#pragma unroll
            for (int i = 0; i < 2; i++) {
                int idx = tid + i * 256;
                int row = idx >> 2, seg = idx & 3;
                const __half2* hp = (const __half2*)&pah[i];
                float2 f[4];
#pragma unroll
                for (int j = 0; j < 4; j++) f[j] = __half22float2(hp[j]);
                uint4 h, l;
                h.x = pack2bf(f[0].x, f[0].y); h.y = pack2bf(f[1].x, f[1].y);
                h.z = pack2bf(f[2].x, f[2].y); h.w = pack2bf(f[3].x, f[3].y);
                l.x = pack2bf(bfres(f[0].x), bfres(f[0].y));
                l.y = pack2bf(bfres(f[1].x), bfres(f[1].y));
                l.z = pack2bf(bfres(f[2].x), bfres(f[2].y));
                l.w = pack2bf(bfres(f[3].x), bfres(f[3].y));
                uint32_t off = row * ROWB + seg * 16;
                *(uint4*)(smem + st * STAGE + off) = h;
                *(uint4*)(smem + st * STAGE + AT + off) = l;
            }
        }
    };
    auto loadB = [&](int ch, int st) {
        const uint32_t base = sb + st * STAGE;
#pragma unroll
        for (int i = 0; i < (N_OUT * 4) / 256; i++) {
            int idx = tid + i * 256;
            int row = idx >> 2, seg = idx & 3;
            size_t g = (size_t)row * K_TOTAL + ch * 32 + seg * 8;
            cp16(base + 2 * AT + row * ROWB + seg * 16, Bhi + g, true);
            cp16(base + 2 * AT + BT + row * ROWB + seg * 16, Blo + g, true);
        }
        CP_COMMIT();
    };
    auto compute = [&](int st) {
        const uint32_t base = sb + st * STAGE;
        const uint32_t aHi = base, aLo = base + AT;
        const uint32_t bHi = base + 2 * AT, bLo = base + 2 * AT + BT;
#pragma unroll
        for (int ks = 0; ks < 2; ks++) {
            const int seg = 2 * ks + (lmat >> 1);
            uint32_t bh[NF][2], bl[NF][2];
#pragma unroll
            for (int p = 0; p < NF / 2; p++) {
                int nrow = wn * WN + p * 16 + lrow + (lmat & 1) * 8;
                uint32_t off = nrow * ROWB + seg * 16;
                uint32_t r0, r1, r2, r3;
                ldsm4(r0, r1, r2, r3, bHi + off);
                bh[2 * p][0] = r0; bh[2 * p + 1][0] = r1;
                bh[2 * p][1] = r2; bh[2 * p + 1][1] = r3;
                ldsm4(r0, r1, r2, r3, bLo + off);
                bl[2 * p][0] = r0; bl[2 * p + 1][0] = r1;
                bl[2 * p][1] = r2; bl[2 * p + 1][1] = r3;
            }
#pragma unroll
            for (int mf = 0; mf < 4; mf++) {
                int arow = wm * 64 + mf * 16 + lrow + (lmat & 1) * 8;
                uint32_t off = arow * ROWB + seg * 16;
                uint32_t ah[4], al[4];
                ldsm4(ah[0], ah[1], ah[2], ah[3], aHi + off);
                ldsm4(al[0], al[1], al[2], al[3], aLo + off);
#pragma unroll
                for (int nf = 0; nf < NF; nf++) {
                    mma_bf16(acc[mf][nf], ah, bh[nf]);
                    mma_bf16(acc[mf][nf], ah, bl[nf]);
                    mma_bf16(acc[mf][nf], al, bh[nf]);
                }
            }
        }
    };

    ldgA(0);
    stsA(0);
    loadB(0, 0);
    CP_WAIT0();
    __syncthreads();
    for (int c = 0; c < NCH; c++) {
        bool more = (c + 1) < NCH;
        if (more) { ldgA(c + 1); loadB(c + 1, (c + 1) & 1); }
        compute(c & 1);
        if (more) {
            stsA((c + 1) & 1);
            CP_WAIT0();
            __syncthreads();
        }
    }

    // Epilogue: fp16 out
    const int r0 = lane >> 2;
    const int c0 = (lane & 3) * 2;
#pragma unroll
    for (int mf = 0; mf < 4; mf++) {
        int row = bm + wm * 64 + mf * 16 + r0;
#pragma unroll
        for (int half = 0; half < 2; half++) {
            int rr = row + half * 8;
            if (rr < M) {
#pragma unroll
                for (int nf = 0; nf < NF; nf++) {
                    int col = wn * WN + nf * 8 + c0;
                    __half2 hv = __floats2half2_rn(acc[mf][nf][half * 2],
                                                   acc[mf][nf][half * 2 + 1]);
                    *(__half2*)&Cout[(size_t)rr * N_OUT + col] = hv;
                }
            }
        }
    }
}

// ---------------------------------------------------------------------------
// CSR pull-mode SpMM over fp16 support, fused bias+relu, fp16 activation out.
// ---------------------------------------------------------------------------
template <int D>
__global__ void spmm_h_kernel(const __half* __restrict__ S, const int2* __restrict__ csr,
                              const int* __restrict__ rowptr, const float* __restrict__ bias,
                              __half* __restrict__ outA) {
    int warp = (blockIdx.x * blockDim.x + threadIdx.x) >> 5;
    int lane = threadIdx.x & 31;
    if (warp >= NN) return;
    int start = __ldg(&rowptr[warp]);
    int end = __ldg(&rowptr[warp + 1]);

    if (D == 128) {
        float4 acc = __ldg((const float4*)bias + lane);
        int e = start;
        for (; e + 1 < end; e += 2) {
            int2 r0 = __ldg(&csr[e]);
            int2 r1 = __ldg(&csr[e + 1]);
            uint2 q0 = __ldg((const uint2*)(S + (size_t)r0.x * 128) + lane);
            uint2 q1 = __ldg((const uint2*)(S + (size_t)r1.x * 128) + lane);
            float w0 = __int_as_float(r0.y), w1 = __int_as_float(r1.y);
            float2 a0 = __half22float2(*(__half2*)&q0.x);
            float2 b0 = __half22float2(*(__half2*)&q0.y);
            float2 a1 = __half22float2(*(__half2*)&q1.x);
            float2 b1 = __half22float2(*(__half2*)&q1.y);
            acc.x = fmaf(w0, a0.x, acc.x); acc.y = fmaf(w0, a0.y, acc.y);
            acc.z = fmaf(w0, b0.x, acc.z); acc.w = fmaf(w0, b0.y, acc.w);
            acc.x = fmaf(w1, a1.x, acc.x); acc.y = fmaf(w1, a1.y, acc.y);
            acc.z = fmaf(w1, b1.x, acc.z); acc.w = fmaf(w1, b1.y, acc.w);
        }
        if (e < end) {
            int2 r0 = __ldg(&csr[e]);
            uint2 q0 = __ldg((const uint2*)(S + (size_t)r0.x * 128) + lane);
            float w0 = __int_as_float(r0.y);
            float2 a0 = __half22float2(*(__half2*)&q0.x);
            float2 b0 = __half22float2(*(__half2*)&q0.y);
            acc.x = fmaf(w0, a0.x, acc.x); acc.y = fmaf(w0, a0.y, acc.y);
            acc.z = fmaf(w0, b0.x, acc.z); acc.w = fmaf(w0, b0.y, acc.w);
        }
        acc.x = fmaxf(acc.x, 0.f); acc.y = fmaxf(acc.y, 0.f);
        acc.z = fmaxf(acc.z, 0.f); acc.w = fmaxf(acc.w, 0.f);
        uint2 o;
        __half2 h0 = __floats2half2_rn(acc.x, acc.y);
        __half2 h1 = __floats2half2_rn(acc.z, acc.w);
        o.x = *(unsigned*)&h0;
        o.y = *(unsigned*)&h1;
        ((uint2*)(outA + (size_t)warp * 128))[lane] = o;
    } else {
        float2 acc = __ldg((const float2*)bias + lane);
        int e = start;
        for (; e + 1 < end; e += 2) {
            int2 r0 = __ldg(&csr[e]);
            int2 r1 = __ldg(&csr[e + 1]);
            unsigned q0 = __ldg((const unsigned*)(S + (size_t)r0.x * 64) + lane);
            unsigned q1 = __ldg((const unsigned*)(S + (size_t)r1.x * 64) + lane);
            float w0 = __int_as_float(r0.y), w1 = __int_as_float(r1.y);
            float2 v0 = __half22float2(*(__half2*)&q0);
            float2 v1 = __half22float2(*(__half2*)&q1);
            acc.x = fmaf(w0, v0.x, acc.x); acc.y = fmaf(w0, v0.y, acc.y);
            acc.x = fmaf(w1, v1.x, acc.x); acc.y = fmaf(w1, v1.y, acc.y);
        }
        if (e < end) {
            int2 r0 = __ldg(&csr[e]);
            unsigned q0 = __ldg((const unsigned*)(S + (size_t)r0.x * 64) + lane);
            float w0 = __int_as_float(r0.y);
            float2 v0 = __half22float2(*(__half2*)&q0);
            acc.x = fmaf(w0, v0.x, acc.x); acc.y = fmaf(w0, v0.y, acc.y);
        }
        acc.x = fmaxf(acc.x, 0.f); acc.y = fmaxf(acc.y, 0.f);
        __half2 h0 = __floats2half2_rn(acc.x, acc.y);
        ((unsigned*)(outA + (size_t)warp * 64))[lane] = *(unsigned*)&h0;
    }
}

// ---------------------------------------------------------------------------
// Final-layer SpMM: fp16 support gather, fp32 accumulate + bias, fp32 out.
// ---------------------------------------------------------------------------
__global__ void spmm_final_kernel(const __half* __restrict__ S, const int2* __restrict__ csr,
                                  const int* __restrict__ rowptr, const float* __restrict__ bias,
                                  float* __restrict__ out) {
    int warp = (blockIdx.x * blockDim.x + threadIdx.x) >> 5;
    int lane = threadIdx.x & 31;
    if (warp >= NN) return;
    int start = __ldg(&rowptr[warp]);
    int end = __ldg(&rowptr[warp + 1]);
    float2 acc = __ldg((const float2*)bias + lane);
    int e = start;
    for (; e + 1 < end; e += 2) {
        int2 r0 = __ldg(&csr[e]);
        int2 r1 = __ldg(&csr[e + 1]);
        unsigned q0 = __ldg((const unsigned*)(S + (size_t)r0.x * 64) + lane);
        unsigned q1 = __ldg((const unsigned*)(S + (size_t)r1.x * 64) + lane);
        float w0 = __int_as_float(r0.y), w1 = __int_as_float(r1.y);
        float2 v0 = __half22float2(*(__half2*)&q0);
        float2 v1 = __half22float2(*(__half2*)&q1);
        acc.x = fmaf(w0, v0.x, acc.x); acc.y = fmaf(w0, v0.y, acc.y);
        acc.x = fmaf(w1, v1.x, acc.x); acc.y = fmaf(w1, v1.y, acc.y);
    }
    if (e < end) {
        int2 r0 = __ldg(&csr[e]);
        unsigned q0 = __ldg((const unsigned*)(S + (size_t)r0.x * 64) + lane);
        float w0 = __int_as_float(r0.y);
        float2 v0 = __half22float2(*(__half2*)&q0);
        acc.x = fmaf(w0, v0.x, acc.x); acc.y = fmaf(w0, v0.y, acc.y);
    }
    *((float2*)(out + (size_t)warp * 64) + lane) = acc;
}

// ---------------------------------------------------------------------------
extern "C" void kernel_launch(void* const* d_in, const int* in_sizes, int n_in,
                              void* d_out, int out_size) {
    const float* x    = (const float*)d_in[0];
    const int*   esrc = (const int*)d_in[1];
    const int*   edst = (const int*)d_in[2];
    const float* ew   = (const float*)d_in[3];
    const float* W1   = (const float*)d_in[4];
    const float* b1   = (const float*)d_in[5];
    const float* W2   = (const float*)d_in[6];
    const float* b2   = (const float*)d_in[7];
    const float* W3   = (const float*)d_in[8];
    const float* b3   = (const float*)d_in[9];
    float* out = (float*)d_out;

    __half *S1h, *A1h, *S2h, *A2h, *S3h;
    __nv_bfloat16 *WH, *WL;
    int *cnt, *pre, *bsum, *btop, *rowptr, *cursor;
    int2* csr;
    cudaGetSymbolAddress((void**)&S1h, g_S1h);
    cudaGetSymbolAddress((void**)&A1h, g_A1h);
    cudaGetSymbolAddress((void**)&S2h, g_S2h);
    cudaGetSymbolAddress((void**)&A2h, g_A2h);
    cudaGetSymbolAddress((void**)&S3h, g_S3h);
    cudaGetSymbolAddress((void**)&WH, g_WH);
    cudaGetSymbolAddress((void**)&WL, g_WL);
    cudaGetSymbolAddress((void**)&cnt, g_cnt);
    cudaGetSymbolAddress((void**)&pre, g_pre);
    cudaGetSymbolAddress((void**)&bsum, g_bsum);
    cudaGetSymbolAddress((void**)&btop, g_btop);
    cudaGetSymbolAddress((void**)&rowptr, g_rowptr);
    cudaGetSymbolAddress((void**)&cursor, g_cursor);
    cudaGetSymbolAddress((void**)&csr, g_csr);

    static cudaStream_t s2strm = nullptr;
    static cudaEvent_t evFork = nullptr, evJoin = nullptr;
    if (s2strm == nullptr) {
        cudaStreamCreateWithFlags(&s2strm, cudaStreamNonBlocking);
        cudaEventCreateWithFlags(&evFork, cudaEventDisableTiming);
        cudaEventCreateWithFlags(&evJoin, cudaEventDisableTiming);
    }

    const int E = NE, M = NN;
    const int gx = (M + 127) / 128;

    cudaFuncSetAttribute(gemm_mma_kernel<128, 256, 0>,
                         cudaFuncAttributeMaxDynamicSharedMemorySize, 81920);
    cudaFuncSetAttribute(gemm_mma_kernel<64, 128, 1>,
                         cudaFuncAttributeMaxDynamicSharedMemorySize, 61440);
    cudaFuncSetAttribute(gemm_mma_kernel<64, 64, 1>,
                         cudaFuncAttributeMaxDynamicSharedMemorySize, 61440);

    // ----- Fork: CSR build + W2/W3 splits on side stream -----
    cudaEventRecord(evFork, 0);
    cudaStreamWaitEvent(s2strm, evFork, 0);
    zero_kernel<<<(NN + 511) / 512, 512, 0, s2strm>>>(cnt, NN);
    count_kernel<<<(E + 511) / 512, 512, 0, s2strm>>>(edst, cnt, E);
    scan_block_kernel<<<NBLK_SCAN, 1024, 0, s2strm>>>(cnt, pre, bsum, NN);
    scan_block_kernel<<<1, 1024, 0, s2strm>>>(bsum, btop, nullptr, NBLK_SCAN);
    add_offsets_kernel<<<(NN + 511) / 512, 512, 0, s2strm>>>(pre, btop, rowptr, cursor, NN);
    scatter_kernel<<<(E + 511) / 512, 512, 0, s2strm>>>(esrc, edst, ew, cursor, csr, E);
    wsplit_kernel<<<(128 * 64 + 255) / 256, 256, 0, s2strm>>>(W2, WH + 32768, WL + 32768, 128, 64);
    wsplit_kernel<<<(64 * 64 + 255) / 256, 256, 0, s2strm>>>(W3, WH + 40960, WL + 40960, 64, 64);
    cudaEventRecord(evJoin, s2strm);

    // ----- Main: W1 split + GEMM1 (fp32 x -> fp16 S1) -----
    wsplit_kernel<<<(256 * 128 + 255) / 256, 256>>>(W1, WH, WL, 256, 128);
    gemm_mma_kernel<128, 256, 0><<<gx, 256, 81920>>>(x, WH, WL, S1h, M);

    // ----- Join, then Layer 1 SpMM (fp16 gather -> fp16 activation) -----
    cudaStreamWaitEvent(0, evJoin, 0);
    spmm_h_kernel<128><<<(NN + 7) / 8, 256>>>(S1h, csr, rowptr, b1, A1h);

    // ----- Layer 2 (fp16 A -> fp16 S2 -> fp16 activation) -----
    gemm_mma_kernel<64, 128, 1><<<gx, 256, 61440>>>(A1h, WH + 32768, WL + 32768, S2h, M);
    spmm_h_kernel<64><<<(NN + 7) / 8, 256>>>(S2h, csr, rowptr, b2, A2h);

    // ----- Layer 3 (fp16 A -> fp16 S3; final spmm fp32 out) -----
    gemm_mma_kernel<64, 64, 1><<<gx, 256, 61440>>>(A2h, WH + 40960, WL + 40960, S3h, M);
    spmm_final_kernel<<<(NN + 7) / 8, 256>>>(S3h, csr, rowptr, b3, out);
}

// round 14
// speedup vs baseline: 1.7396x; 1.1601x over previous
#include <cuda_runtime.h>
#include <cuda_fp16.h>
#include <cstdint>

#define NN 100000
#define NE 1600000
#define NBLK_SCAN 98   // ceil(100000/1024)

// ---------------------------------------------------------------------------
// Scratch (static device arrays; allocation-free per harness rules).
// ---------------------------------------------------------------------------
__device__ __half g_S1h[(size_t)NN * 128]; // layer-1 support (fp16)
__device__ __half g_A1h[(size_t)NN * 128]; // layer-1 activation (fp16)
__device__ __half g_S2h[(size_t)NN * 64];  // layer-2 support (fp16)
__device__ __half g_A2h[(size_t)NN * 64];  // layer-2 activation (fp16)
__device__ __half g_S3h[(size_t)NN * 64];  // layer-3 support (fp16)
__device__ __half g_Wh[45056];             // fp16 weights, transposed (W1T|W2T|W3T)
__device__ int   g_cnt[NN];
__device__ int   g_pre[NN];
__device__ int   g_bsum[1024];
__device__ int   g_btop[1024];
__device__ int   g_rowptr[NN + 1];
__device__ int   g_cursor[NN];
__device__ int2  g_csr[NE];

// ---------------------------------------------------------------------------
// Helpers
// ---------------------------------------------------------------------------
__device__ __forceinline__ uint32_t smem_u32(const void* p) {
    uint32_t a;
    asm("{ .reg .u64 t; cvta.to.shared.u64 t, %1; cvt.u32.u64 %0, t; }" : "=r"(a) : "l"(p));
    return a;
}
__device__ __forceinline__ void cp16(uint32_t s, const void* g, bool pred) {
    asm volatile("cp.async.cg.shared.global [%0], [%1], 16, %2;"
                 :: "r"(s), "l"(g), "r"(pred ? 16 : 0));
}
#define CP_COMMIT() asm volatile("cp.async.commit_group;" ::: "memory")
#define CP_WAIT0()  asm volatile("cp.async.wait_group 0;" ::: "memory")
#define CP_WAIT1()  asm volatile("cp.async.wait_group 1;" ::: "memory")

__device__ __forceinline__ void ldsm4(uint32_t& r0, uint32_t& r1, uint32_t& r2, uint32_t& r3,
                                      uint32_t addr) {
    asm volatile("ldmatrix.sync.aligned.m8n8.x4.shared.b16 {%0,%1,%2,%3}, [%4];"
                 : "=r"(r0), "=r"(r1), "=r"(r2), "=r"(r3) : "r"(addr));
}
__device__ __forceinline__ void mma_f16(float* d, const uint32_t* a, const uint32_t* b) {
    asm volatile(
        "mma.sync.aligned.m16n8k16.row.col.f32.f16.f16.f32 "
        "{%0,%1,%2,%3}, {%4,%5,%6,%7}, {%8,%9}, {%0,%1,%2,%3};"
        : "+f"(d[0]), "+f"(d[1]), "+f"(d[2]), "+f"(d[3])
        : "r"(a[0]), "r"(a[1]), "r"(a[2]), "r"(a[3]), "r"(b[0]), "r"(b[1]));
}

// ---------------------------------------------------------------------------
// CSR build kernels (known good)
// ---------------------------------------------------------------------------
__global__ void zero_kernel(int* __restrict__ p, int n) {
    int i = blockIdx.x * blockDim.x + threadIdx.x;
    if (i < n) p[i] = 0;
}
__global__ void count_kernel(const int* __restrict__ dst, int* __restrict__ cnt, int E) {
    int e = blockIdx.x * blockDim.x + threadIdx.x;
    if (e < E) atomicAdd(&cnt[__ldg(&dst[e])], 1);
}
__global__ void scan_block_kernel(const int* __restrict__ in, int* __restrict__ outx,
                                  int* __restrict__ sums, int n) {
    __shared__ int s[2][1024];
    int tid = threadIdx.x;
    int i = blockIdx.x * 1024 + tid;
    int v = (i < n) ? in[i] : 0;
    int pin = 0;
    s[0][tid] = v;
    __syncthreads();
#pragma unroll
    for (int off = 1; off < 1024; off <<= 1) {
        int t = s[pin][tid] + ((tid >= off) ? s[pin][tid - off] : 0);
        s[pin ^ 1][tid] = t;
        pin ^= 1;
        __syncthreads();
    }
    if (i < n) outx[i] = s[pin][tid] - v;
    if (sums != nullptr && tid == 1023) sums[blockIdx.x] = s[pin][1023];
}
__global__ void add_offsets_kernel(const int* __restrict__ pre, const int* __restrict__ top,
                                   int* __restrict__ rowptr, int* __restrict__ cursor, int n) {
    int i = blockIdx.x * blockDim.x + threadIdx.x;
    if (i < n) {
        int v = pre[i] + __ldg(&top[i >> 10]);
        rowptr[i] = v;
        cursor[i] = v;
    }
    if (i == 0) rowptr[n] = NE;
}
__global__ void scatter_kernel(const int* __restrict__ src, const int* __restrict__ dst,
                               const float* __restrict__ w, int* __restrict__ cursor,
                               int2* __restrict__ csr, int E) {
    int e = blockIdx.x * blockDim.x + threadIdx.x;
    if (e >= E) return;
    int d = __ldg(&dst[e]);
    int pos = atomicAdd(&cursor[d], 1);
    csr[pos] = make_int2(__ldg(&src[e]), __float_as_int(__ldg(&w[e])));
}

// W[K,N] row-major -> fp16 [N,K] k-major
__global__ void wconv_kernel(const float* __restrict__ W, __half* __restrict__ Wh,
                             int K, int N) {
    int i = blockIdx.x * blockDim.x + threadIdx.x;
    if (i >= K * N) return;
    int n = i / K, k = i % K;
    Wh[(size_t)n * K + k] = __float2half_rn(__ldg(&W[(size_t)k * N + n]));
}

// ---------------------------------------------------------------------------
// HMMA fp16 GEMM: C[M,N_OUT] = A[M,K] @ B[N_OUT,K]^T, fp32 accum, fp16 out.
// AMODE 0: A fp32, converted in regs (pipelined LDG/STS).
// AMODE 1: A fp16 via cp.async.
// BM=128, BK=32, double-buffered. 8 warps (2m x 4n), warp tile 64 x (N_OUT/4).
// Rows padded to 80B -> ldmatrix conflict-free.
// ---------------------------------------------------------------------------
template <int N_OUT, int K_TOTAL, int AMODE>
__global__ __launch_bounds__(256, 2)
void gemm_mma_kernel(const void* __restrict__ Ain, const __half* __restrict__ Bh,
                     __half* __restrict__ Cout, int M) {
    constexpr int NCH = K_TOTAL / 32;
    constexpr int ROWB = 80;
    constexpr int AT = 128 * ROWB;       // 10240
    constexpr int BT = N_OUT * ROWB;
    constexpr int STAGE = AT + BT;
    constexpr int WN = N_OUT / 4;
    constexpr int NF = WN / 8;

    extern __shared__ char smem[];
    const uint32_t sb = smem_u32(smem);
    const int tid = threadIdx.x;
    const int wid = tid >> 5, lane = tid & 31;
    const int wm = wid & 1, wn = wid >> 1;
    const int bm = blockIdx.x * 128;
    const int lrow = lane & 7;
    const int lmat = lane >> 3;

    float acc[4][NF][4];
#pragma unroll
    for (int mf = 0; mf < 4; mf++)
#pragma unroll
        for (int nf = 0; nf < NF; nf++)
#pragma unroll
            for (int j = 0; j < 4; j++) acc[mf][nf][j] = 0.f;

    float4 paf[4];   // AMODE 0 prefetch regs

    auto ldgA = [&](int ch) {
        const float* Af = (const float*)Ain;
#pragma unroll
        for (int i = 0; i < 4; i++) {
            int idx = tid + i * 256;
            int row = idx >> 3, seg = idx & 7;
            paf[i] = make_float4(0.f, 0.f, 0.f, 0.f);
            if (bm + row < M)
                paf[i] = __ldg((const float4*)&Af[(size_t)(bm + row) * K_TOTAL + ch * 32 + seg * 4]);
        }
    };
    auto stsA = [&](int st) {
#pragma unroll
        for (int i = 0; i < 4; i++) {
            int idx = tid + i * 256;
            int row = idx >> 3, seg = idx & 7;
            float4 v = paf[i];
            __half2 h0 = __floats2half2_rn(v.x, v.y);
            __half2 h1 = __floats2half2_rn(v.z, v.w);
            uint2 h = make_uint2(*(unsigned*)&h0, *(unsigned*)&h1);
            *(uint2*)(smem + st * STAGE + row * ROWB + seg * 8) = h;
        }
    };
    auto loadA_cp = [&](int ch, int st) {
        const __half* Ah = (const __half*)Ain;
        const uint32_t base = sb + st * STAGE;
#pragma unroll
        for (int i = 0; i < 2; i++) {
            int idx = tid + i * 256;
            int row = idx >> 2, seg = idx & 3;
            bool p = (bm + row) < M;
            cp16(base + row * ROWB + seg * 16,
                 Ah + (size_t)(bm + row) * K_TOTAL + ch * 32 + seg * 8, p);
        }
    };
    auto loadB = [&](int ch, int st) {
        const uint32_t base = sb + st * STAGE;
#pragma unroll
        for (int i = 0; i < (N_OUT * 4) / 256; i++) {
            int idx = tid + i * 256;
            int row = idx >> 2, seg = idx & 3;
            cp16(base + AT + row * ROWB + seg * 16,
                 Bh + (size_t)row * K_TOTAL + ch * 32 + seg * 8, true);
        }
        CP_COMMIT();
    };
    auto compute = [&](int st) {
        const uint32_t aB = sb + st * STAGE;
        const uint32_t bB = aB + AT;
#pragma unroll
        for (int ks = 0; ks < 2; ks++) {
            const int seg = 2 * ks + (lmat >> 1);
            uint32_t bf[NF][2];
#pragma unroll
            for (int p = 0; p < NF / 2; p++) {
                int nrow = wn * WN + p * 16 + lrow + (lmat & 1) * 8;
                uint32_t off = nrow * ROWB + seg * 16;
                uint32_t r0, r1, r2, r3;
                ldsm4(r0, r1, r2, r3, bB + off);
                bf[2 * p][0] = r0; bf[2 * p + 1][0] = r1;
                bf[2 * p][1] = r2; bf[2 * p + 1][1] = r3;
            }
#pragma unroll
            for (int mf = 0; mf < 4; mf++) {
                int arow = wm * 64 + mf * 16 + lrow + (lmat & 1) * 8;
                uint32_t off = arow * ROWB + seg * 16;
                uint32_t af[4];
                ldsm4(af[0], af[1], af[2], af[3], aB + off);
#pragma unroll
                for (int nf = 0; nf < NF; nf++)
                    mma_f16(acc[mf][nf], af, bf[nf]);
            }
        }
    };

    if (AMODE == 0) {
        ldgA(0);
        stsA(0);
        loadB(0, 0);
        CP_WAIT0();
        __syncthreads();
        for (int c = 0; c < NCH; c++) {
            bool more = (c + 1) < NCH;
            if (more) { ldgA(c + 1); loadB(c + 1, (c + 1) & 1); }
            compute(c & 1);
            if (more) {
                stsA((c + 1) & 1);
                CP_WAIT0();
                __syncthreads();
            }
        }
    } else {
        loadA_cp(0, 0);
        loadB(0, 0);
        for (int c = 0; c < NCH; c++) {
            if (c + 1 < NCH) {
                loadA_cp(c + 1, (c + 1) & 1);
                loadB(c + 1, (c + 1) & 1);
                CP_WAIT1();
            } else {
                CP_WAIT0();
            }
            __syncthreads();
            compute(c & 1);
            __syncthreads();
        }
    }

    // Epilogue: fp16 out
    const int r0 = lane >> 2;
    const int c0 = (lane & 3) * 2;
#pragma unroll
    for (int mf = 0; mf < 4; mf++) {
        int row = bm + wm * 64 + mf * 16 + r0;
#pragma unroll
        for (int half = 0; half < 2; half++) {
            int rr = row + half * 8;
            if (rr < M) {
#pragma unroll
                for (int nf = 0; nf < NF; nf++) {
                    int col = wn * WN + nf * 8 + c0;
                    __half2 hv = __floats2half2_rn(acc[mf][nf][half * 2],
                                                   acc[mf][nf][half * 2 + 1]);
                    *(__half2*)&Cout[(size_t)rr * N_OUT + col] = hv;
                }
            }
        }
    }
}

// ---------------------------------------------------------------------------
// CSR pull-mode SpMM over fp16 support, fused bias+relu, fp16 activation out.
// ---------------------------------------------------------------------------
template <int D>
__global__ void spmm_h_kernel(const __half* __restrict__ S, const int2* __restrict__ csr,
                              const int* __restrict__ rowptr, const float* __restrict__ bias,
                              __half* __restrict__ outA) {
    int warp = (blockIdx.x * blockDim.x + threadIdx.x) >> 5;
    int lane = threadIdx.x & 31;
    if (warp >= NN) return;
    int start = __ldg(&rowptr[warp]);
    int end = __ldg(&rowptr[warp + 1]);

    if (D == 128) {
        float4 acc = __ldg((const float4*)bias + lane);
        int e = start;
        for (; e + 1 < end; e += 2) {
            int2 r0 = __ldg(&csr[e]);
            int2 r1 = __ldg(&csr[e + 1]);
            uint2 q0 = __ldg((const uint2*)(S + (size_t)r0.x * 128) + lane);
            uint2 q1 = __ldg((const uint2*)(S + (size_t)r1.x * 128) + lane);
            float w0 = __int_as_float(r0.y), w1 = __int_as_float(r1.y);
            float2 a0 = __half22float2(*(__half2*)&q0.x);
            float2 b0 = __half22float2(*(__half2*)&q0.y);
            float2 a1 = __half22float2(*(__half2*)&q1.x);
            float2 b1 = __half22float2(*(__half2*)&q1.y);
            acc.x = fmaf(w0, a0.x, acc.x); acc.y = fmaf(w0, a0.y, acc.y);
            acc.z = fmaf(w0, b0.x, acc.z); acc.w = fmaf(w0, b0.y, acc.w);
            acc.x = fmaf(w1, a1.x, acc.x); acc.y = fmaf(w1, a1.y, acc.y);
            acc.z = fmaf(w1, b1.x, acc.z); acc.w = fmaf(w1, b1.y, acc.w);
        }
        if (e < end) {
            int2 r0 = __ldg(&csr[e]);
            uint2 q0 = __ldg((const uint2*)(S + (size_t)r0.x * 128) + lane);
            float w0 = __int_as_float(r0.y);
            float2 a0 = __half22float2(*(__half2*)&q0.x);
            float2 b0 = __half22float2(*(__half2*)&q0.y);
            acc.x = fmaf(w0, a0.x, acc.x); acc.y = fmaf(w0, a0.y, acc.y);
            acc.z = fmaf(w0, b0.x, acc.z); acc.w = fmaf(w0, b0.y, acc.w);
        }
        acc.x = fmaxf(acc.x, 0.f); acc.y = fmaxf(acc.y, 0.f);
        acc.z = fmaxf(acc.z, 0.f); acc.w = fmaxf(acc.w, 0.f);
        uint2 o;
        __half2 h0 = __floats2half2_rn(acc.x, acc.y);
        __half2 h1 = __floats2half2_rn(acc.z, acc.w);
        o.x = *(unsigned*)&h0;
        o.y = *(unsigned*)&h1;
        ((uint2*)(outA + (size_t)warp * 128))[lane] = o;
    } else {
        float2 acc = __ldg((const float2*)bias + lane);
        int e = start;
        for (; e + 1 < end; e += 2) {
            int2 r0 = __ldg(&csr[e]);
            int2 r1 = __ldg(&csr[e + 1]);
            unsigned q0 = __ldg((const unsigned*)(S + (size_t)r0.x * 64) + lane);
            unsigned q1 = __ldg((const unsigned*)(S + (size_t)r1.x * 64) + lane);
            float w0 = __int_as_float(r0.y), w1 = __int_as_float(r1.y);
            float2 v0 = __half22float2(*(__half2*)&q0);
            float2 v1 = __half22float2(*(__half2*)&q1);
            acc.x = fmaf(w0, v0.x, acc.x); acc.y = fmaf(w0, v0.y, acc.y);
            acc.x = fmaf(w1, v1.x, acc.x); acc.y = fmaf(w1, v1.y, acc.y);
        }
        if (e < end) {
            int2 r0 = __ldg(&csr[e]);
            unsigned q0 = __ldg((const unsigned*)(S + (size_t)r0.x * 64) + lane);
            float w0 = __int_as_float(r0.y);
            float2 v0 = __half22float2(*(__half2*)&q0);
            acc.x = fmaf(w0, v0.x, acc.x); acc.y = fmaf(w0, v0.y, acc.y);
        }
        acc.x = fmaxf(acc.x, 0.f); acc.y = fmaxf(acc.y, 0.f);
        __half2 h0 = __floats2half2_rn(acc.x, acc.y);
        ((unsigned*)(outA + (size_t)warp * 64))[lane] = *(unsigned*)&h0;
    }
}

// ---------------------------------------------------------------------------
// Final-layer SpMM: fp16 support gather, fp32 accumulate + bias, fp32 out.
// ---------------------------------------------------------------------------
__global__ void spmm_final_kernel(const __half* __restrict__ S, const int2* __restrict__ csr,
                                  const int* __restrict__ rowptr, const float* __restrict__ bias,
                                  float* __restrict__ out) {
    int warp = (blockIdx.x * blockDim.x + threadIdx.x) >> 5;
    int lane = threadIdx.x & 31;
    if (warp >= NN) return;
    int start = __ldg(&rowptr[warp]);
    int end = __ldg(&rowptr[warp + 1]);
    float2 acc = __ldg((const float2*)bias + lane);
    int e = start;
    for (; e + 1 < end; e += 2) {
        int2 r0 = __ldg(&csr[e]);
        int2 r1 = __ldg(&csr[e + 1]);
        unsigned q0 = __ldg((const unsigned*)(S + (size_t)r0.x * 64) + lane);
        unsigned q1 = __ldg((const unsigned*)(S + (size_t)r1.x * 64) + lane);
        float w0 = __int_as_float(r0.y), w1 = __int_as_float(r1.y);
        float2 v0 = __half22float2(*(__half2*)&q0);
        float2 v1 = __half22float2(*(__half2*)&q1);
        acc.x = fmaf(w0, v0.x, acc.x); acc.y = fmaf(w0, v0.y, acc.y);
        acc.x = fmaf(w1, v1.x, acc.x); acc.y = fmaf(w1, v1.y, acc.y);
    }
    if (e < end) {
        int2 r0 = __ldg(&csr[e]);
        unsigned q0 = __ldg((const unsigned*)(S + (size_t)r0.x * 64) + lane);
        float w0 = __int_as_float(r0.y);
        float2 v0 = __half22float2(*(__half2*)&q0);
        acc.x = fmaf(w0, v0.x, acc.x); acc.y = fmaf(w0, v0.y, acc.y);
    }
    *((float2*)(out + (size_t)warp * 64) + lane) = acc;
}

// ---------------------------------------------------------------------------
extern "C" void kernel_launch(void* const* d_in, const int* in_sizes, int n_in,
                              void* d_out, int out_size) {
    const float* x    = (const float*)d_in[0];
    const int*   esrc = (const int*)d_in[1];
    const int*   edst = (const int*)d_in[2];
    const float* ew   = (const float*)d_in[3];
    const float* W1   = (const float*)d_in[4];
    const float* b1   = (const float*)d_in[5];
    const float* W2   = (const float*)d_in[6];
    const float* b2   = (const float*)d_in[7];
    const float* W3   = (const float*)d_in[8];
    const float* b3   = (const float*)d_in[9];
    float* out = (float*)d_out;

    __half *S1h, *A1h, *S2h, *A2h, *S3h, *Wh;
    int *cnt, *pre, *bsum, *btop, *rowptr, *cursor;
    int2* csr;
    cudaGetSymbolAddress((void**)&S1h, g_S1h);
    cudaGetSymbolAddress((void**)&A1h, g_A1h);
    cudaGetSymbolAddress((void**)&S2h, g_S2h);
    cudaGetSymbolAddress((void**)&A2h, g_A2h);
    cudaGetSymbolAddress((void**)&S3h, g_S3h);
    cudaGetSymbolAddress((void**)&Wh, g_Wh);
    cudaGetSymbolAddress((void**)&cnt, g_cnt);
    cudaGetSymbolAddress((void**)&pre, g_pre);
    cudaGetSymbolAddress((void**)&bsum, g_bsum);
    cudaGetSymbolAddress((void**)&btop, g_btop);
    cudaGetSymbolAddress((void**)&rowptr, g_rowptr);
    cudaGetSymbolAddress((void**)&cursor, g_cursor);
    cudaGetSymbolAddress((void**)&csr, g_csr);

    static cudaStream_t s2strm = nullptr;
    static cudaEvent_t evFork = nullptr, evJoin = nullptr;
    if (s2strm == nullptr) {
        cudaStreamCreateWithFlags(&s2strm, cudaStreamNonBlocking);
        cudaEventCreateWithFlags(&evFork, cudaEventDisableTiming);
        cudaEventCreateWithFlags(&evJoin, cudaEventDisableTiming);
    }

    const int E = NE, M = NN;
    const int gx = (M + 127) / 128;

    // smem: GEMM1 stage=(10240+10240)*2=40960; GEMM2/3 stage=(10240+5120)*2=30720
    cudaFuncSetAttribute(gemm_mma_kernel<128, 256, 0>,
                         cudaFuncAttributeMaxDynamicSharedMemorySize, 40960);
    cudaFuncSetAttribute(gemm_mma_kernel<64, 128, 1>,
                         cudaFuncAttributeMaxDynamicSharedMemorySize, 30720);
    cudaFuncSetAttribute(gemm_mma_kernel<64, 64, 1>,
                         cudaFuncAttributeMaxDynamicSharedMemorySize, 30720);

    // ----- Fork: CSR build + W2/W3 converts on side stream -----
    cudaEventRecord(evFork, 0);
    cudaStreamWaitEvent(s2strm, evFork, 0);
    zero_kernel<<<(NN + 511) / 512, 512, 0, s2strm>>>(cnt, NN);
    count_kernel<<<(E + 511) / 512, 512, 0, s2strm>>>(edst, cnt, E);
    scan_block_kernel<<<NBLK_SCAN, 1024, 0, s2strm>>>(cnt, pre, bsum, NN);
    scan_block_kernel<<<1, 1024, 0, s2strm>>>(bsum, btop, nullptr, NBLK_SCAN);
    add_offsets_kernel<<<(NN + 511) / 512, 512, 0, s2strm>>>(pre, btop, rowptr, cursor, NN);
    scatter_kernel<<<(E + 511) / 512, 512, 0, s2strm>>>(esrc, edst, ew, cursor, csr, E);
    wconv_kernel<<<(128 * 64 + 255) / 256, 256, 0, s2strm>>>(W2, Wh + 32768, 128, 64);
    wconv_kernel<<<(64 * 64 + 255) / 256, 256, 0, s2strm>>>(W3, Wh + 40960, 64, 64);
    cudaEventRecord(evJoin, s2strm);

    // ----- Main: W1 convert + GEMM1 (fp32 x -> fp16 S1) -----
    wconv_kernel<<<(256 * 128 + 255) / 256, 256>>>(W1, Wh, 256, 128);
    gemm_mma_kernel<128, 256, 0><<<gx, 256, 40960>>>(x, Wh, S1h, M);

    // ----- Join, then Layer 1 SpMM (fp16 gather -> fp16 activation) -----
    cudaStreamWaitEvent(0, evJoin, 0);
    spmm_h_kernel<128><<<(NN + 7) / 8, 256>>>(S1h, csr, rowptr, b1, A1h);

    // ----- Layer 2 -----
    gemm_mma_kernel<64, 128, 1><<<gx, 256, 30720>>>(A1h, Wh + 32768, S2h, M);
    spmm_h_kernel<64><<<(NN + 7) / 8, 256>>>(S2h, csr, rowptr, b2, A2h);

    // ----- Layer 3 -----
    gemm_mma_kernel<64, 64, 1><<<gx, 256, 30720>>>(A2h, Wh + 40960, S3h, M);
    spmm_final_kernel<<<(NN + 7) / 8, 256>>>(S3h, csr, rowptr, b3, out);
}